// round 7
// baseline (speedup 1.0000x reference)
#include <cuda_runtime.h>
#include <cuda_fp16.h>
#include <stdint.h>
#include <math.h>

// ---------------------------------------------------------------------------
// GCLSTM (K=1 ChebConv -> edge data unused). fp16 HMMA, gates fused in GEMM1.
//   prep : A16 = fp16([x | h])  [50000 x 512]
//   GEMM1 (fused): acc = A16 @ Wt^T + bias, cols gate-interleaved (4j+g);
//                  epilogue stages acc in smem, computes gates ->
//                  h0, c0 (fp32) and R = relu(h0) (fp16). No P tensor.
//   GEMM2: out = R @ WlinT^T + b_lin     (M=50000, N=256, K=256)
// GEMM config: CTA 128x256, warp 64x64 (8 warps), BK=32, 4-stage cp.async.
// Output tuple: [out | h0 | c0], each 50000*256 fp32.
// ---------------------------------------------------------------------------

#define NNODES 50000

__device__ __half g_A16[(size_t)NNODES * 512];
__device__ __half g_R[(size_t)NNODES * 256];
__device__ __half g_Wt[1024 * 512];              // [4j+g][k]
__device__ __half g_WlT[256 * 256];
__device__ float  g_bias[1024];                  // [4j+g]

// ---------------------------------------------------------------------------
__device__ __forceinline__ uint32_t smem_u32(const void* p) {
    uint32_t a;
    asm("{ .reg .u64 t; cvta.to.shared.u64 t, %1; cvt.u32.u64 %0, t; }"
        : "=r"(a) : "l"(p));
    return a;
}
__device__ __forceinline__ void ldm4(uint32_t* a, uint32_t addr) {
    asm volatile("ldmatrix.sync.aligned.m8n8.x4.shared.b16 {%0,%1,%2,%3}, [%4];"
        : "=r"(a[0]), "=r"(a[1]), "=r"(a[2]), "=r"(a[3]) : "r"(addr));
}
__device__ __forceinline__ void mma16816(float* d, const uint32_t* a, const uint32_t* b) {
    asm volatile(
        "mma.sync.aligned.m16n8k16.row.col.f32.f16.f16.f32 "
        "{%0,%1,%2,%3},{%4,%5,%6,%7},{%8,%9},{%0,%1,%2,%3};"
        : "+f"(d[0]), "+f"(d[1]), "+f"(d[2]), "+f"(d[3])
        : "r"(a[0]), "r"(a[1]), "r"(a[2]), "r"(a[3]), "r"(b[0]), "r"(b[1]));
}
__device__ __forceinline__ void cp16(uint32_t dst, const void* src) {
    asm volatile("cp.async.cg.shared.global [%0], [%1], 16;" :: "r"(dst), "l"(src));
}
__device__ __forceinline__ void cp_commit() { asm volatile("cp.async.commit_group;"); }
template <int N>
__device__ __forceinline__ void cp_wait() {
    asm volatile("cp.async.wait_group %0;" :: "n"(N));
}

__device__ __forceinline__ float sigf(float x)  { return 1.f / (1.f + __expf(-x)); }
__device__ __forceinline__ float tanf_(float x) { return 2.f / (1.f + __expf(-2.f * x)) - 1.f; }

// ---------------------------------------------------------------------------
// HMMA GEMM: BM=128, BN=256, BK=32, 8 warps (2m x 4n), warp tile 64x64,
// 4-stage cp.async. A fp16 [M,K], B fp16 [Ntot,K], acc = A @ B^T + bias.
// GATES=true : fused GCLSTM epilogue (h0, c0, R); Cv unused.
// GATES=false: plain fp32 epilogue into Cv.
// ---------------------------------------------------------------------------
#define ABUF (128 * 80)
#define BBUF (256 * 80)
#define STG  (ABUF + BBUF)
#define SMEM_DYN (4 * STG)          // 122880 B; staging needs 128*264*2=67584 B

template <bool GATES>
__global__ void __launch_bounds__(256, 1)
hmma_gemm(const __half* __restrict__ A16, const __half* __restrict__ B,
          float* __restrict__ Cv, const float* __restrict__ bias,
          int M, int Ntot, int K,
          const float* __restrict__ c_in,
          const float* __restrict__ wci, const float* __restrict__ wcf,
          const float* __restrict__ wco,
          float* __restrict__ hout, float* __restrict__ cout,
          __half* __restrict__ Rout)
{
    extern __shared__ __align__(16) char usm[];
    __shared__ float sbias[256];
    __shared__ float swci[64], swcf[64], swco[64];

    const int tid  = threadIdx.x;
    const int lane = tid & 31;
    const int wid  = tid >> 5;
    const int warpm = wid >> 2;
    const int warpn = wid & 3;
    const int m0 = blockIdx.y * 128;
    const int n0 = blockIdx.x * 256;
    const int jb = n0 >> 2;              // global hidden-unit base (GATES)

    const uint32_t smb = smem_u32(usm);

    sbias[tid] = bias[n0 + tid];
    if (GATES && tid < 64) {
        swci[tid] = wci[jb + tid];
        swcf[tid] = wcf[jb + tid];
        swco[tid] = wco[jb + tid];
    }

    float acc[4][8][4];
#pragma unroll
    for (int mt = 0; mt < 4; ++mt)
#pragma unroll
        for (int nt = 0; nt < 8; ++nt)
#pragma unroll
            for (int e = 0; e < 4; ++e) acc[mt][nt][e] = 0.f;

    const int nch = K >> 5;

    auto issue = [&](int kc, int st) {
        const uint32_t ab = smb + st * STG;
        const uint32_t bb = ab + ABUF;
#pragma unroll
        for (int q = 0; q < 2; ++q) {
            int u = tid + q * 256;
            int r = u >> 2, kq = u & 3;
            int gr = m0 + r;
            if (gr < M)
                cp16(ab + r * 80 + kq * 16,
                     A16 + (size_t)gr * K + kc * 32 + kq * 8);
        }
#pragma unroll
        for (int q = 0; q < 4; ++q) {
            int u = tid + q * 256;
            int r = u >> 2, kq = u & 3;
            cp16(bb + r * 80 + kq * 16,
                 B + (size_t)(n0 + r) * K + kc * 32 + kq * 8);
        }
    };

    issue(0, 0); cp_commit();
    issue(1, 1); cp_commit();
    issue(2, 2); cp_commit();
    cp_wait<2>();
    __syncthreads();

    const int arow = warpm * 64 + (lane & 15);
    const int aoff = (lane >> 4) * 8;
    const int brow = warpn * 64 + ((lane >> 4) << 3) + (lane & 7);
    const int boff = ((lane >> 3) & 1) * 8;

    for (int t = 0; t < nch; ++t) {
        if (t + 3 < nch) issue(t + 3, (t + 3) & 3);
        cp_commit();

        const int st = t & 3;
        const uint32_t ab = smb + st * STG + arow * 80;
        const uint32_t bb = smb + st * STG + ABUF + brow * 80;
#pragma unroll
        for (int ks = 0; ks < 2; ++ks) {
            const int k0 = ks * 16;
            uint32_t afr[4][4], bfr[8][2];
#pragma unroll
            for (int mt = 0; mt < 4; ++mt)
                ldm4(afr[mt], ab + mt * 16 * 80 + (k0 + aoff) * 2);
#pragma unroll
            for (int np = 0; np < 4; ++np) {
                uint32_t f[4];
                ldm4(f, bb + np * 16 * 80 + (k0 + boff) * 2);
                bfr[np * 2][0] = f[0]; bfr[np * 2][1] = f[1];
                bfr[np * 2 + 1][0] = f[2]; bfr[np * 2 + 1][1] = f[3];
            }
#pragma unroll
            for (int mt = 0; mt < 4; ++mt)
#pragma unroll
                for (int nt = 0; nt < 8; ++nt)
                    mma16816(acc[mt][nt], afr[mt], bfr[nt]);
        }

        cp_wait<2>();
        __syncthreads();
    }

    if (GATES) {
        // ---- stage full 128x256 acc tile as fp16 (stride 264 halves) ----
        __half* stg = (__half*)usm;
#pragma unroll
        for (int mt = 0; mt < 4; ++mt) {
            int r0 = warpm * 64 + mt * 16 + (lane >> 2);
            int r1 = r0 + 8;
#pragma unroll
            for (int nt = 0; nt < 8; ++nt) {
                int cc = warpn * 64 + nt * 8 + (lane & 3) * 2;
                float b0 = sbias[cc], b1 = sbias[cc + 1];
                *(__half2*)(stg + r0 * 264 + cc) =
                    __floats2half2_rn(acc[mt][nt][0] + b0, acc[mt][nt][1] + b1);
                *(__half2*)(stg + r1 * 264 + cc) =
                    __floats2half2_rn(acc[mt][nt][2] + b0, acc[mt][nt][3] + b1);
            }
        }
        __syncthreads();

        // ---- gates: 128 rows x 64 units, coalesced writes ----
#pragma unroll 1
        for (int i = 0; i < 32; ++i) {
            int row = wid * 16 + (i >> 1);          // 0..127
            int j   = (i & 1) * 32 + lane;          // 0..63
            int m = m0 + row;
            if (m < M) {
                uint2 pv = *(uint2*)(stg + row * 264 + j * 4);
                float2 p01 = __half22float2(*(__half2*)&pv.x);
                float2 p23 = __half22float2(*(__half2*)&pv.y);
                int jg = jb + j;
                size_t off = (size_t)m * 256 + jg;
                float cv = __ldg(c_in + off);
                float I = sigf(p01.x + swci[j] * cv);
                float F = sigf(p01.y + swcf[j] * cv);
                float T = tanf_(p23.x);
                float Cn = F * cv + I * T;
                float O = sigf(p23.y + swco[j] * Cn);
                float H = O * tanf_(Cn);
                hout[off] = H;
                cout[off] = Cn;
                Rout[off] = __float2half_rn(fmaxf(H, 0.f));
            }
        }
    } else {
        // ---- plain epilogue ----
#pragma unroll
        for (int mt = 0; mt < 4; ++mt) {
            int r0 = m0 + warpm * 64 + mt * 16 + (lane >> 2);
            int r1 = r0 + 8;
#pragma unroll
            for (int nt = 0; nt < 8; ++nt) {
                int cl = warpn * 64 + nt * 8 + (lane & 3) * 2;
                int cg = n0 + cl;
                float b0 = sbias[cl], b1 = sbias[cl + 1];
                if (r0 < M)
                    *(float2*)(Cv + (size_t)r0 * Ntot + cg) =
                        make_float2(acc[mt][nt][0] + b0, acc[mt][nt][1] + b1);
                if (r1 < M)
                    *(float2*)(Cv + (size_t)r1 * Ntot + cg) =
                        make_float2(acc[mt][nt][2] + b0, acc[mt][nt][3] + b1);
            }
        }
    }
}

// ---------------------------------------------------------------------------
__global__ void prep_a16(const float* __restrict__ x, const float* __restrict__ h)
{
    int u = blockIdx.x * blockDim.x + threadIdx.x;
    if (u >= NNODES * 64) return;
    int n = u >> 6;
    int kq = (u & 63) << 3;
    const float* src = (kq < 256) ? (x + (size_t)n * 256 + kq)
                                  : (h + (size_t)n * 256 + kq - 256);
    float4 f0 = *(const float4*)(src);
    float4 f1 = *(const float4*)(src + 4);
    __half2 h0 = __floats2half2_rn(f0.x, f0.y);
    __half2 h1 = __floats2half2_rn(f0.z, f0.w);
    __half2 h2 = __floats2half2_rn(f1.x, f1.y);
    __half2 h3 = __floats2half2_rn(f1.z, f1.w);
    uint4 v;
    v.x = *(uint32_t*)&h0; v.y = *(uint32_t*)&h1;
    v.z = *(uint32_t*)&h2; v.w = *(uint32_t*)&h3;
    *(uint4*)(g_A16 + (size_t)n * 512 + kq) = v;
}

// ---------------------------------------------------------------------------
// Pack: g_Wt[4j+g][k] (gate-interleaved), g_WlT[n][k] = Wlin[k][n],
//       g_bias[4j+g] = bth_g[j] + b_g[j].
// ---------------------------------------------------------------------------
__global__ void pack_kernel(
    const float* __restrict__ Wi, const float* __restrict__ Wf,
    const float* __restrict__ Wc, const float* __restrict__ Wo,
    const float* __restrict__ Ti, const float* __restrict__ Tf,
    const float* __restrict__ Tc, const float* __restrict__ To,
    const float* __restrict__ bthi, const float* __restrict__ bthf,
    const float* __restrict__ bthc, const float* __restrict__ btho,
    const float* __restrict__ bi, const float* __restrict__ bf,
    const float* __restrict__ bc, const float* __restrict__ bo,
    const float* __restrict__ Wlin)
{
    int idx = blockIdx.x * blockDim.x + threadIdx.x;
    if (idx < 524288) {                       // g_Wt[4j+g][k]
        int n = idx >> 9, k = idx & 511;
        int g = n & 3, j = n >> 2;
        float v;
        if (k < 256) {
            const float* W = (g == 0) ? Wi : (g == 1) ? Wf : (g == 2) ? Wc : Wo;
            v = W[k * 256 + j];
        } else {
            const float* T = (g == 0) ? Ti : (g == 1) ? Tf : (g == 2) ? Tc : To;
            v = T[(k - 256) * 256 + j];
        }
        g_Wt[idx] = __float2half_rn(v);
    } else if (idx < 524288 + 65536) {        // g_WlT[n][k] = Wlin[k][n]
        int i2 = idx - 524288;
        int n = i2 >> 8, k = i2 & 255;
        g_WlT[i2] = __float2half_rn(Wlin[k * 256 + n]);
    } else if (idx < 524288 + 65536 + 1024) { // g_bias interleaved
        int n = idx - 524288 - 65536;
        int g = n & 3, j = n >> 2;
        const float* bth = (g == 0) ? bthi : (g == 1) ? bthf : (g == 2) ? bthc : btho;
        const float* bb  = (g == 0) ? bi   : (g == 1) ? bf   : (g == 2) ? bc   : bo;
        g_bias[n] = bth[j] + bb[j];
    }
}

// ---------------------------------------------------------------------------
extern "C" void kernel_launch(void* const* d_in, const int* in_sizes, int n_in,
                              void* d_out, int out_size)
{
    const float* x    = (const float*)d_in[0];
    // d_in[1] edge_index, d_in[2] edge_weight -> unused (K=1 ChebConv)
    const float* h    = (const float*)d_in[3];
    const float* c    = (const float*)d_in[4];
    const float* Wi   = (const float*)d_in[5];
    const float* Wf   = (const float*)d_in[6];
    const float* Wc   = (const float*)d_in[7];
    const float* Wo   = (const float*)d_in[8];
    const float* Ti   = (const float*)d_in[9];
    const float* Tf   = (const float*)d_in[10];
    const float* Tc   = (const float*)d_in[11];
    const float* To   = (const float*)d_in[12];
    const float* bthi = (const float*)d_in[13];
    const float* bthf = (const float*)d_in[14];
    const float* bthc = (const float*)d_in[15];
    const float* btho = (const float*)d_in[16];
    const float* wci  = (const float*)d_in[17];
    const float* wcf  = (const float*)d_in[18];
    const float* wco  = (const float*)d_in[19];
    const float* bi   = (const float*)d_in[20];
    const float* bf   = (const float*)d_in[21];
    const float* bc   = (const float*)d_in[22];
    const float* bo   = (const float*)d_in[23];
    const float* Wlin = (const float*)d_in[24];
    const float* blin = (const float*)d_in[25];
    float* out = (float*)d_out;

    float *pBias;
    __half *pA16, *pWt, *pWlT, *pR;
    cudaGetSymbolAddress((void**)&pBias, g_bias);
    cudaGetSymbolAddress((void**)&pA16, g_A16);
    cudaGetSymbolAddress((void**)&pWt, g_Wt);
    cudaGetSymbolAddress((void**)&pWlT, g_WlT);
    cudaGetSymbolAddress((void**)&pR, g_R);

    cudaFuncSetAttribute(hmma_gemm<true>,
                         cudaFuncAttributeMaxDynamicSharedMemorySize, SMEM_DYN);
    cudaFuncSetAttribute(hmma_gemm<false>,
                         cudaFuncAttributeMaxDynamicSharedMemorySize, SMEM_DYN);

    // 1) pack weights/bias (gate-interleaved)
    pack_kernel<<<(524288 + 65536 + 1024 + 255) / 256, 256>>>(
        Wi, Wf, Wc, Wo, Ti, Tf, Tc, To,
        bthi, bthf, bthc, btho, bi, bf, bc, bo, Wlin);

    // 2) A16 = fp16([x|h])
    prep_a16<<<(NNODES * 64 + 255) / 256, 256>>>(x, h);

    const size_t elems = (size_t)NNODES * 256;

    // 3) GEMM1 + fused gates -> h0, c0, R
    hmma_gemm<true><<<dim3(4, (NNODES + 127) / 128), 256, SMEM_DYN>>>(
        pA16, pWt, nullptr, pBias, NNODES, 1024, 512,
        c, wci, wcf, wco, out + elems, out + 2 * elems, pR);

    // 4) GEMM2: out = R @ WlinT^T + b_lin
    hmma_gemm<false><<<dim3(1, (NNODES + 127) / 128), 256, SMEM_DYN>>>(
        pR, pWlT, out, blin, NNODES, 256, 256,
        nullptr, nullptr, nullptr, nullptr, nullptr, nullptr, nullptr);
}

// round 8
// speedup vs baseline: 1.6247x; 1.6247x over previous
#include <cuda_runtime.h>
#include <cuda_fp16.h>
#include <stdint.h>
#include <math.h>

// ---------------------------------------------------------------------------
// GCLSTM (K=1 ChebConv -> edge data unused). fp16 HMMA path, chunked pipeline:
//   prep : A16 = fp16([x | h])
//   per M-chunk (12500 rows), two streams:
//     GEMM1: P = A16 @ Wt^T + bias (fp16)      [default stream]
//     gates: h0, c0 (fp32), R (fp16)           [side stream]
//     GEMM2: out = R @ WlinT^T + b_lin         [side stream]
//   gates+GEMM2 of chunk i overlap GEMM1 of chunk i+1.
// Output tuple: [out | h0 | c0], each 50000*256 fp32.
// ---------------------------------------------------------------------------

#define NNODES 50000
#define NCH    4
#define CROWS  12500

__device__ __half g_A16[(size_t)NNODES * 512];
__device__ __half g_P[(size_t)NNODES * 1024];
__device__ __half g_R[(size_t)NNODES * 256];
__device__ __half g_Wt[1024 * 512];
__device__ __half g_WlT[256 * 256];
__device__ float  g_bias[1024];

// ---------------------------------------------------------------------------
__device__ __forceinline__ uint32_t smem_u32(const void* p) {
    uint32_t a;
    asm("{ .reg .u64 t; cvta.to.shared.u64 t, %1; cvt.u32.u64 %0, t; }"
        : "=r"(a) : "l"(p));
    return a;
}
__device__ __forceinline__ void ldm4(uint32_t* a, uint32_t addr) {
    asm volatile("ldmatrix.sync.aligned.m8n8.x4.shared.b16 {%0,%1,%2,%3}, [%4];"
        : "=r"(a[0]), "=r"(a[1]), "=r"(a[2]), "=r"(a[3]) : "r"(addr));
}
__device__ __forceinline__ void ldm2(uint32_t* b, uint32_t addr) {
    asm volatile("ldmatrix.sync.aligned.m8n8.x2.shared.b16 {%0,%1}, [%2];"
        : "=r"(b[0]), "=r"(b[1]) : "r"(addr));
}
__device__ __forceinline__ void mma16816(float* d, const uint32_t* a, const uint32_t* b) {
    asm volatile(
        "mma.sync.aligned.m16n8k16.row.col.f32.f16.f16.f32 "
        "{%0,%1,%2,%3},{%4,%5,%6,%7},{%8,%9},{%0,%1,%2,%3};"
        : "+f"(d[0]), "+f"(d[1]), "+f"(d[2]), "+f"(d[3])
        : "r"(a[0]), "r"(a[1]), "r"(a[2]), "r"(a[3]), "r"(b[0]), "r"(b[1]));
}
__device__ __forceinline__ void cp16(uint32_t dst, const void* src) {
    asm volatile("cp.async.cg.shared.global [%0], [%1], 16;" :: "r"(dst), "l"(src));
}
__device__ __forceinline__ void cp_commit() { asm volatile("cp.async.commit_group;"); }
template <int N>
__device__ __forceinline__ void cp_wait() {
    asm volatile("cp.async.wait_group %0;" :: "n"(N));
}

__device__ __forceinline__ float sigf(float x)  { return 1.f / (1.f + __expf(-x)); }
__device__ __forceinline__ float tanf_(float x) { return 2.f / (1.f + __expf(-2.f * x)) - 1.f; }

// ---------------------------------------------------------------------------
// GEMM1: BM=128, BN=256, BK=32, 8 warps (2m x 4n), warp 64x64, 4-stage.
// A fp16 [M,512], B fp16 [1024,512]; P(fp16) = A @ B^T + bias.
// ---------------------------------------------------------------------------
#define ABUF1 (128 * 80)
#define BBUF1 (256 * 80)
#define STG1  (ABUF1 + BBUF1)
#define SMEM1 (4 * STG1)           // 122880 B

__global__ void __launch_bounds__(256, 1)
gemm1_kernel(const __half* __restrict__ A16, const __half* __restrict__ B,
             __half* __restrict__ C, const float* __restrict__ bias, int M)
{
    extern __shared__ __align__(16) char usm[];
    __shared__ float sbias[256];

    const int tid  = threadIdx.x;
    const int lane = tid & 31;
    const int wid  = tid >> 5;
    const int warpm = wid >> 2;
    const int warpn = wid & 3;
    const int m0 = blockIdx.y * 128;
    const int n0 = blockIdx.x * 256;
    const int K = 512, Ntot = 1024;

    const uint32_t smb = smem_u32(usm);
    sbias[tid] = bias[n0 + tid];

    float acc[4][8][4];
#pragma unroll
    for (int mt = 0; mt < 4; ++mt)
#pragma unroll
        for (int nt = 0; nt < 8; ++nt)
#pragma unroll
            for (int e = 0; e < 4; ++e) acc[mt][nt][e] = 0.f;

    auto issue = [&](int kc, int st) {
        const uint32_t ab = smb + st * STG1;
        const uint32_t bb = ab + ABUF1;
#pragma unroll
        for (int q = 0; q < 2; ++q) {
            int u = tid + q * 256;
            int r = u >> 2, kq = u & 3;
            int gr = m0 + r;
            if (gr < M)
                cp16(ab + r * 80 + kq * 16,
                     A16 + (size_t)gr * K + kc * 32 + kq * 8);
        }
#pragma unroll
        for (int q = 0; q < 4; ++q) {
            int u = tid + q * 256;
            int r = u >> 2, kq = u & 3;
            cp16(bb + r * 80 + kq * 16,
                 B + (size_t)(n0 + r) * K + kc * 32 + kq * 8);
        }
    };

    issue(0, 0); cp_commit();
    issue(1, 1); cp_commit();
    issue(2, 2); cp_commit();
    cp_wait<2>();
    __syncthreads();

    const int arow = warpm * 64 + (lane & 15);
    const int aoff = (lane >> 4) * 8;
    const int brow = warpn * 64 + ((lane >> 4) << 3) + (lane & 7);
    const int boff = ((lane >> 3) & 1) * 8;

    const int nch = K >> 5;       // 16
    for (int t = 0; t < nch; ++t) {
        if (t + 3 < nch) issue(t + 3, (t + 3) & 3);
        cp_commit();

        const int st = t & 3;
        const uint32_t ab = smb + st * STG1 + arow * 80;
        const uint32_t bb = smb + st * STG1 + ABUF1 + brow * 80;
#pragma unroll
        for (int ks = 0; ks < 2; ++ks) {
            const int k0 = ks * 16;
            uint32_t afr[4][4], bfr[8][2];
#pragma unroll
            for (int mt = 0; mt < 4; ++mt)
                ldm4(afr[mt], ab + mt * 16 * 80 + (k0 + aoff) * 2);
#pragma unroll
            for (int np = 0; np < 4; ++np) {
                uint32_t f[4];
                ldm4(f, bb + np * 16 * 80 + (k0 + boff) * 2);
                bfr[np * 2][0] = f[0]; bfr[np * 2][1] = f[1];
                bfr[np * 2 + 1][0] = f[2]; bfr[np * 2 + 1][1] = f[3];
            }
#pragma unroll
            for (int mt = 0; mt < 4; ++mt)
#pragma unroll
                for (int nt = 0; nt < 8; ++nt)
                    mma16816(acc[mt][nt], afr[mt], bfr[nt]);
        }

        cp_wait<2>();
        __syncthreads();
    }

#pragma unroll
    for (int mt = 0; mt < 4; ++mt) {
        int r0 = m0 + warpm * 64 + mt * 16 + (lane >> 2);
        int r1 = r0 + 8;
#pragma unroll
        for (int nt = 0; nt < 8; ++nt) {
            int cl = warpn * 64 + nt * 8 + (lane & 3) * 2;
            int cg = n0 + cl;
            float b0 = sbias[cl], b1 = sbias[cl + 1];
            if (r0 < M)
                *(__half2*)(C + (size_t)r0 * Ntot + cg) =
                    __floats2half2_rn(acc[mt][nt][0] + b0, acc[mt][nt][1] + b1);
            if (r1 < M)
                *(__half2*)(C + (size_t)r1 * Ntot + cg) =
                    __floats2half2_rn(acc[mt][nt][2] + b0, acc[mt][nt][3] + b1);
        }
    }
}

// ---------------------------------------------------------------------------
// GEMM2: BM=BN=128, BK=32, 8 warps (2m x 4n), warp 64x32, 3-stage.
// out(fp32) = R @ WlinT^T + b_lin.
// ---------------------------------------------------------------------------
#define TB2 (128 * 80)
#define SMEM2 (6 * TB2)            // 61440 B

__global__ void __launch_bounds__(256)
gemm2_kernel(const __half* __restrict__ A16, const __half* __restrict__ B,
             float* __restrict__ C, const float* __restrict__ bias, int M)
{
    extern __shared__ __align__(16) char usm[];
    __shared__ float sbias[128];

    const int tid  = threadIdx.x;
    const int lane = tid & 31;
    const int wid  = tid >> 5;
    const int warpm = wid >> 2;
    const int warpn = wid & 3;
    const int m0 = blockIdx.y * 128;
    const int n0 = blockIdx.x * 128;
    const int K = 256, Ntot = 256;

    const uint32_t asb = smem_u32(usm);
    const uint32_t bsb = asb + 3 * TB2;

    for (int i = tid; i < 128; i += 256) sbias[i] = bias[n0 + i];

    float acc[4][4][4];
#pragma unroll
    for (int mt = 0; mt < 4; ++mt)
#pragma unroll
        for (int nt = 0; nt < 4; ++nt)
#pragma unroll
            for (int e = 0; e < 4; ++e) acc[mt][nt][e] = 0.f;

    auto issue = [&](int kc, int st) {
#pragma unroll
        for (int q = 0; q < 2; ++q) {
            int u = tid + q * 256;
            int r = u >> 2, kq = u & 3;
            int gr = m0 + r;
            if (gr < M)
                cp16(asb + st * TB2 + r * 80 + kq * 16,
                     A16 + (size_t)gr * K + kc * 32 + kq * 8);
        }
#pragma unroll
        for (int q = 0; q < 2; ++q) {
            int u = tid + q * 256;
            int r = u >> 2, kq = u & 3;
            cp16(bsb + st * TB2 + r * 80 + kq * 16,
                 B + (size_t)(n0 + r) * K + kc * 32 + kq * 8);
        }
    };

    issue(0, 0); cp_commit();
    issue(1, 1); cp_commit();

    const int mrow = warpm * 64 + (lane & 15);
    const int nrow = warpn * 32 + (lane & 7);
    const int aksel = (lane >> 4) * 8;
    const int bksel = ((lane >> 3) & 1) * 8;

    const int nch = K >> 5;        // 8
    for (int t = 0; t < nch; ++t) {
        if (t + 2 < nch) issue(t + 2, (t + 2) % 3);
        cp_commit();
        cp_wait<2>();
        __syncthreads();

        const int st = t % 3;
        const uint32_t abase = asb + st * TB2 + mrow * 80;
        const uint32_t bbase = bsb + st * TB2 + nrow * 80;
#pragma unroll
        for (int ks = 0; ks < 2; ++ks) {
            const int k0 = ks * 16;
            uint32_t afr[4][4], bfr[4][2];
#pragma unroll
            for (int mt = 0; mt < 4; ++mt)
                ldm4(afr[mt], abase + mt * 16 * 80 + (k0 + aksel) * 2);
#pragma unroll
            for (int nt = 0; nt < 4; ++nt)
                ldm2(bfr[nt], bbase + nt * 8 * 80 + (k0 + bksel) * 2);
#pragma unroll
            for (int mt = 0; mt < 4; ++mt)
#pragma unroll
                for (int nt = 0; nt < 4; ++nt)
                    mma16816(acc[mt][nt], afr[mt], bfr[nt]);
        }
        __syncthreads();
    }

#pragma unroll
    for (int mt = 0; mt < 4; ++mt) {
        int r0 = m0 + warpm * 64 + mt * 16 + (lane >> 2);
        int r1 = r0 + 8;
#pragma unroll
        for (int nt = 0; nt < 4; ++nt) {
            int cl = warpn * 32 + nt * 8 + (lane & 3) * 2;
            int cg = n0 + cl;
            float b0 = sbias[cl], b1 = sbias[cl + 1];
            if (r0 < M)
                *(float2*)(C + (size_t)r0 * Ntot + cg) =
                    make_float2(acc[mt][nt][0] + b0, acc[mt][nt][1] + b1);
            if (r1 < M)
                *(float2*)(C + (size_t)r1 * Ntot + cg) =
                    make_float2(acc[mt][nt][2] + b0, acc[mt][nt][3] + b1);
        }
    }
}

// ---------------------------------------------------------------------------
__global__ void prep_a16(const float* __restrict__ x, const float* __restrict__ h)
{
    int u = blockIdx.x * blockDim.x + threadIdx.x;
    if (u >= NNODES * 64) return;
    int n = u >> 6;
    int kq = (u & 63) << 3;
    const float* src = (kq < 256) ? (x + (size_t)n * 256 + kq)
                                  : (h + (size_t)n * 256 + kq - 256);
    float4 f0 = *(const float4*)(src);
    float4 f1 = *(const float4*)(src + 4);
    __half2 h0 = __floats2half2_rn(f0.x, f0.y);
    __half2 h1 = __floats2half2_rn(f0.z, f0.w);
    __half2 h2 = __floats2half2_rn(f1.x, f1.y);
    __half2 h3 = __floats2half2_rn(f1.z, f1.w);
    uint4 v;
    v.x = *(uint32_t*)&h0; v.y = *(uint32_t*)&h1;
    v.z = *(uint32_t*)&h2; v.w = *(uint32_t*)&h3;
    *(uint4*)(g_A16 + (size_t)n * 512 + kq) = v;
}

// ---------------------------------------------------------------------------
__global__ void pack_kernel(
    const float* __restrict__ Wi, const float* __restrict__ Wf,
    const float* __restrict__ Wc, const float* __restrict__ Wo,
    const float* __restrict__ Ti, const float* __restrict__ Tf,
    const float* __restrict__ Tc, const float* __restrict__ To,
    const float* __restrict__ bthi, const float* __restrict__ bthf,
    const float* __restrict__ bthc, const float* __restrict__ btho,
    const float* __restrict__ bi, const float* __restrict__ bf,
    const float* __restrict__ bc, const float* __restrict__ bo,
    const float* __restrict__ Wlin)
{
    int idx = blockIdx.x * blockDim.x + threadIdx.x;
    if (idx < 524288) {                       // g_Wt[n][k] = Wall[k][n]
        int n = idx >> 9, k = idx & 511;
        int g = n >> 8, jj = n & 255;
        float v;
        if (k < 256) {
            const float* W = (g == 0) ? Wi : (g == 1) ? Wf : (g == 2) ? Wc : Wo;
            v = W[k * 256 + jj];
        } else {
            const float* T = (g == 0) ? Ti : (g == 1) ? Tf : (g == 2) ? Tc : To;
            v = T[(k - 256) * 256 + jj];
        }
        g_Wt[idx] = __float2half_rn(v);
    } else if (idx < 524288 + 65536) {        // g_WlT[n][k] = Wlin[k][n]
        int i2 = idx - 524288;
        int n = i2 >> 8, k = i2 & 255;
        g_WlT[i2] = __float2half_rn(Wlin[k * 256 + n]);
    } else if (idx < 524288 + 65536 + 1024) { // g_bias
        int j = idx - 524288 - 65536;
        int g = j >> 8, jj = j & 255;
        const float* bth = (g == 0) ? bthi : (g == 1) ? bthf : (g == 2) ? bthc : btho;
        const float* bb  = (g == 0) ? bi   : (g == 1) ? bf   : (g == 2) ? bc   : bo;
        g_bias[j] = bth[jj] + bb[jj];
    }
}

// ---------------------------------------------------------------------------
// Gates from fp16 P chunk: 8 cols/thread.
// ---------------------------------------------------------------------------
__global__ void gates_kernel(const __half* __restrict__ P_,
                             const float* __restrict__ c_in,
                             const float* __restrict__ wci,
                             const float* __restrict__ wcf,
                             const float* __restrict__ wco,
                             float* __restrict__ h_out,
                             float* __restrict__ c_out,
                             __half* __restrict__ R_out,
                             int rows)
{
    int u = blockIdx.x * blockDim.x + threadIdx.x;
    if (u >= rows * 32) return;
    int n = u >> 5;
    int j = (u & 31) << 3;
    const __half* P = P_ + (size_t)n * 1024;

    uint4 vi = *(const uint4*)(P + j);
    uint4 vf = *(const uint4*)(P + 256 + j);
    uint4 vc = *(const uint4*)(P + 512 + j);
    uint4 vo = *(const uint4*)(P + 768 + j);
    float4 c0 = *(const float4*)(c_in + (size_t)n * 256 + j);
    float4 c1 = *(const float4*)(c_in + (size_t)n * 256 + j + 4);
    float4 wi0 = *(const float4*)(wci + j), wi1 = *(const float4*)(wci + j + 4);
    float4 wf0 = *(const float4*)(wcf + j), wf1 = *(const float4*)(wcf + j + 4);
    float4 wo0 = *(const float4*)(wco + j), wo1 = *(const float4*)(wco + j + 4);

    float pi[8], pf[8], pc[8], po[8];
    {
        const uint32_t* a = &vi.x;
        const uint32_t* b = &vf.x;
        const uint32_t* cc = &vc.x;
        const uint32_t* d = &vo.x;
#pragma unroll
        for (int q = 0; q < 4; ++q) {
            float2 t;
            t = __half22float2(*(const __half2*)&a[q]);  pi[2*q] = t.x; pi[2*q+1] = t.y;
            t = __half22float2(*(const __half2*)&b[q]);  pf[2*q] = t.x; pf[2*q+1] = t.y;
            t = __half22float2(*(const __half2*)&cc[q]); pc[2*q] = t.x; pc[2*q+1] = t.y;
            t = __half22float2(*(const __half2*)&d[q]);  po[2*q] = t.x; po[2*q+1] = t.y;
        }
    }
    float cv[8]  = {c0.x, c0.y, c0.z, c0.w, c1.x, c1.y, c1.z, c1.w};
    float wia[8] = {wi0.x, wi0.y, wi0.z, wi0.w, wi1.x, wi1.y, wi1.z, wi1.w};
    float wfa[8] = {wf0.x, wf0.y, wf0.z, wf0.w, wf1.x, wf1.y, wf1.z, wf1.w};
    float woa[8] = {wo0.x, wo0.y, wo0.z, wo0.w, wo1.x, wo1.y, wo1.z, wo1.w};

    float H[8], Cn[8];
#pragma unroll
    for (int e = 0; e < 8; ++e) {
        float I = sigf(pi[e] + wia[e] * cv[e]);
        float F = sigf(pf[e] + wfa[e] * cv[e]);
        float T = tanf_(pc[e]);
        Cn[e] = F * cv[e] + I * T;
        float O = sigf(po[e] + woa[e] * Cn[e]);
        H[e] = O * tanf_(Cn[e]);
    }

    size_t off = (size_t)n * 256 + j;
    *(float4*)(h_out + off)     = make_float4(H[0], H[1], H[2], H[3]);
    *(float4*)(h_out + off + 4) = make_float4(H[4], H[5], H[6], H[7]);
    *(float4*)(c_out + off)     = make_float4(Cn[0], Cn[1], Cn[2], Cn[3]);
    *(float4*)(c_out + off + 4) = make_float4(Cn[4], Cn[5], Cn[6], Cn[7]);

    uint4 rv;
    __half2 r01 = __floats2half2_rn(fmaxf(H[0], 0.f), fmaxf(H[1], 0.f));
    __half2 r23 = __floats2half2_rn(fmaxf(H[2], 0.f), fmaxf(H[3], 0.f));
    __half2 r45 = __floats2half2_rn(fmaxf(H[4], 0.f), fmaxf(H[5], 0.f));
    __half2 r67 = __floats2half2_rn(fmaxf(H[6], 0.f), fmaxf(H[7], 0.f));
    rv.x = *(uint32_t*)&r01; rv.y = *(uint32_t*)&r23;
    rv.z = *(uint32_t*)&r45; rv.w = *(uint32_t*)&r67;
    *(uint4*)(R_out + off) = rv;
}

// ---------------------------------------------------------------------------
extern "C" void kernel_launch(void* const* d_in, const int* in_sizes, int n_in,
                              void* d_out, int out_size)
{
    const float* x    = (const float*)d_in[0];
    // d_in[1] edge_index, d_in[2] edge_weight -> unused (K=1 ChebConv)
    const float* h    = (const float*)d_in[3];
    const float* c    = (const float*)d_in[4];
    const float* Wi   = (const float*)d_in[5];
    const float* Wf   = (const float*)d_in[6];
    const float* Wc   = (const float*)d_in[7];
    const float* Wo   = (const float*)d_in[8];
    const float* Ti   = (const float*)d_in[9];
    const float* Tf   = (const float*)d_in[10];
    const float* Tc   = (const float*)d_in[11];
    const float* To   = (const float*)d_in[12];
    const float* bthi = (const float*)d_in[13];
    const float* bthf = (const float*)d_in[14];
    const float* bthc = (const float*)d_in[15];
    const float* btho = (const float*)d_in[16];
    const float* wci  = (const float*)d_in[17];
    const float* wcf  = (const float*)d_in[18];
    const float* wco  = (const float*)d_in[19];
    const float* bi   = (const float*)d_in[20];
    const float* bf   = (const float*)d_in[21];
    const float* bc   = (const float*)d_in[22];
    const float* bo   = (const float*)d_in[23];
    const float* Wlin = (const float*)d_in[24];
    const float* blin = (const float*)d_in[25];
    float* out = (float*)d_out;

    float *pBias;
    __half *pA16, *pP, *pWt, *pWlT, *pR;
    cudaGetSymbolAddress((void**)&pBias, g_bias);
    cudaGetSymbolAddress((void**)&pA16, g_A16);
    cudaGetSymbolAddress((void**)&pP, g_P);
    cudaGetSymbolAddress((void**)&pWt, g_Wt);
    cudaGetSymbolAddress((void**)&pWlT, g_WlT);
    cudaGetSymbolAddress((void**)&pR, g_R);

    cudaFuncSetAttribute(gemm1_kernel,
                         cudaFuncAttributeMaxDynamicSharedMemorySize, SMEM1);
    cudaFuncSetAttribute(gemm2_kernel,
                         cudaFuncAttributeMaxDynamicSharedMemorySize, SMEM2);

    // one-time host-side stream/event setup (no device memory involved)
    static cudaStream_t s2 = nullptr;
    static cudaEvent_t evFork, evPack, e1[NCH], e2[NCH];
    if (!s2) {
        cudaStreamCreateWithFlags(&s2, cudaStreamNonBlocking);
        cudaEventCreateWithFlags(&evFork, cudaEventDisableTiming);
        cudaEventCreateWithFlags(&evPack, cudaEventDisableTiming);
        for (int i = 0; i < NCH; ++i) {
            cudaEventCreateWithFlags(&e1[i], cudaEventDisableTiming);
            cudaEventCreateWithFlags(&e2[i], cudaEventDisableTiming);
        }
    }

    // fork side stream from default
    cudaEventRecord(evFork, 0);
    cudaStreamWaitEvent(s2, evFork, 0);

    // pack on s2 overlapped with prep on default
    pack_kernel<<<(524288 + 65536 + 1024 + 255) / 256, 256, 0, s2>>>(
        Wi, Wf, Wc, Wo, Ti, Tf, Tc, To,
        bthi, bthf, bthc, btho, bi, bf, bc, bo, Wlin);
    cudaEventRecord(evPack, s2);

    prep_a16<<<(NNODES * 64 + 255) / 256, 256>>>(x, h);
    cudaStreamWaitEvent(0, evPack, 0);   // default needs weights for GEMM1

    const size_t elems = (size_t)NNODES * 256;
    float* hout = out + elems;
    float* cout = out + 2 * elems;

    for (int ch = 0; ch < NCH; ++ch) {
        const size_t r0 = (size_t)ch * CROWS;

        // GEMM1 chunk on default stream
        gemm1_kernel<<<dim3(4, (CROWS + 127) / 128), 256, SMEM1>>>(
            pA16 + r0 * 512, pWt, pP + r0 * 1024, pBias, CROWS);
        cudaEventRecord(e1[ch], 0);

        // gates + GEMM2 chunk on side stream
        cudaStreamWaitEvent(s2, e1[ch], 0);
        gates_kernel<<<(CROWS * 32 + 255) / 256, 256, 0, s2>>>(
            pP + r0 * 1024, c + r0 * 256, wci, wcf, wco,
            hout + r0 * 256, cout + r0 * 256, pR + r0 * 256, CROWS);
        gemm2_kernel<<<dim3(2, (CROWS + 127) / 128), 256, SMEM2, s2>>>(
            pR + r0 * 256, pWlT, out + r0 * 256, blin, CROWS);
        cudaEventRecord(e2[ch], s2);
    }

    // join side stream back into default
    for (int ch = 0; ch < NCH; ++ch)
        cudaStreamWaitEvent(0, e2[ch], 0);
}

// round 9
// speedup vs baseline: 1.6624x; 1.0232x over previous
#include <cuda_runtime.h>
#include <cuda_fp16.h>
#include <stdint.h>
#include <math.h>

// ---------------------------------------------------------------------------
// GCLSTM (K=1 ChebConv -> edge data unused). fp16 HMMA, register-pipelined.
//   prep : A16 = fp16([x | h])
//   GEMM1: P(fp16) = A16 @ Wt^T + bias   (M=50000, N=1024, K=512)
//   gates: h0, c0 (fp32), R (fp16)
//   GEMM2: out = R @ WlinT^T + b_lin     (M=50000, N=256, K=256)
// GEMM: BM=128, BN=128, BK=32, 8 warps (2m x 4n), warp 64x32, 3-stage
// cp.async + register fragment double-buffering (CUTLASS sm80 mainloop).
// Output tuple: [out | h0 | c0], each 50000*256 fp32.
// ---------------------------------------------------------------------------

#define NNODES 50000

__device__ __half g_A16[(size_t)NNODES * 512];
__device__ __half g_P[(size_t)NNODES * 1024];
__device__ __half g_R[(size_t)NNODES * 256];
__device__ __half g_Wt[1024 * 512];
__device__ __half g_WlT[256 * 256];
__device__ float  g_bias[1024];

// ---------------------------------------------------------------------------
__device__ __forceinline__ uint32_t smem_u32(const void* p) {
    uint32_t a;
    asm("{ .reg .u64 t; cvta.to.shared.u64 t, %1; cvt.u32.u64 %0, t; }"
        : "=r"(a) : "l"(p));
    return a;
}
__device__ __forceinline__ void ldm4(uint32_t* a, uint32_t addr) {
    asm volatile("ldmatrix.sync.aligned.m8n8.x4.shared.b16 {%0,%1,%2,%3}, [%4];"
        : "=r"(a[0]), "=r"(a[1]), "=r"(a[2]), "=r"(a[3]) : "r"(addr));
}
__device__ __forceinline__ void mma16816(float* d, const uint32_t* a, const uint32_t* b) {
    asm volatile(
        "mma.sync.aligned.m16n8k16.row.col.f32.f16.f16.f32 "
        "{%0,%1,%2,%3},{%4,%5,%6,%7},{%8,%9},{%0,%1,%2,%3};"
        : "+f"(d[0]), "+f"(d[1]), "+f"(d[2]), "+f"(d[3])
        : "r"(a[0]), "r"(a[1]), "r"(a[2]), "r"(a[3]), "r"(b[0]), "r"(b[1]));
}
__device__ __forceinline__ void cp16(uint32_t dst, const void* src) {
    asm volatile("cp.async.cg.shared.global [%0], [%1], 16;" :: "r"(dst), "l"(src));
}
__device__ __forceinline__ void cp_commit() { asm volatile("cp.async.commit_group;"); }
template <int N>
__device__ __forceinline__ void cp_wait() {
    asm volatile("cp.async.wait_group %0;" :: "n"(N));
}

__device__ __forceinline__ float sigf(float x)  { return 1.f / (1.f + __expf(-x)); }
__device__ __forceinline__ float tanf_(float x) { return 2.f / (1.f + __expf(-2.f * x)) - 1.f; }

// ---------------------------------------------------------------------------
// Register-pipelined HMMA GEMM. BM=BN=128, BK=32. 3 smem stages.
// A fp16 [M,K], B fp16 [Ntot,K]; C = A @ B^T + bias (HALF_OUT -> fp16 C).
// ---------------------------------------------------------------------------
#define TBUF  (128 * 80)            // one tile (A or B) per stage: 10240 B
#define STGB  (2 * TBUF)            // stage = A + B
#define SMEMG (3 * STGB)            // 61440 B

template <bool HALF_OUT>
__global__ void __launch_bounds__(256, 1)
hmma_gemm(const __half* __restrict__ A16, const __half* __restrict__ B,
          void* __restrict__ Cv, const float* __restrict__ bias,
          int M, int Ntot, int K)
{
    extern __shared__ __align__(16) char usm[];
    __shared__ float sbias[128];

    const int tid  = threadIdx.x;
    const int lane = tid & 31;
    const int wid  = tid >> 5;
    const int warpm = wid >> 2;          // 0..1 (64 rows each)
    const int warpn = wid & 3;           // 0..3 (32 cols each)
    const int m0 = blockIdx.y * 128;
    const int n0 = blockIdx.x * 128;

    const uint32_t smb = smem_u32(usm);

    for (int i = tid; i < 128; i += 256) sbias[i] = bias[n0 + i];

    float acc[4][4][4];
#pragma unroll
    for (int mt = 0; mt < 4; ++mt)
#pragma unroll
        for (int nt = 0; nt < 4; ++nt)
#pragma unroll
            for (int e = 0; e < 4; ++e) acc[mt][nt][e] = 0.f;

    const int nch = K >> 5;

    auto issue = [&](int kc, int st) {
        const uint32_t ab = smb + st * STGB;
        const uint32_t bb = ab + TBUF;
#pragma unroll
        for (int q = 0; q < 2; ++q) {
            int u = tid + q * 256;
            int r = u >> 2, kq = u & 3;
            int gr = m0 + r;
            if (gr < M)
                cp16(ab + r * 80 + kq * 16,
                     A16 + (size_t)gr * K + kc * 32 + kq * 8);
        }
#pragma unroll
        for (int q = 0; q < 2; ++q) {
            int u = tid + q * 256;
            int r = u >> 2, kq = u & 3;
            cp16(bb + r * 80 + kq * 16,
                 B + (size_t)(n0 + r) * K + kc * 32 + kq * 8);
        }
    };

    // fragment double buffers
    uint32_t afr[2][4][4];
    uint32_t bfr[2][4][2];

    const int arow = warpm * 64 + (lane & 15);
    const int aoff = (lane >> 4) * 8;
    const int brow = warpn * 32 + ((lane >> 4) << 3) + (lane & 7); // 16 B-rows
    const int boff = ((lane >> 3) & 1) * 8;

    auto ldfrags = [&](int buf, int st, int k0) {
        const uint32_t ab = smb + st * STGB + arow * 80 + (k0 + aoff) * 2;
        const uint32_t bb = smb + st * STGB + TBUF + brow * 80 + (k0 + boff) * 2;
#pragma unroll
        for (int mt = 0; mt < 4; ++mt)
            ldm4(afr[buf][mt], ab + mt * 16 * 80);
#pragma unroll
        for (int np = 0; np < 2; ++np) {
            uint32_t f[4];
            ldm4(f, bb + np * 16 * 80);
            bfr[buf][np * 2][0]     = f[0]; bfr[buf][np * 2][1]     = f[1];
            bfr[buf][np * 2 + 1][0] = f[2]; bfr[buf][np * 2 + 1][1] = f[3];
        }
    };
    auto domma = [&](int buf) {
#pragma unroll
        for (int mt = 0; mt < 4; ++mt)
#pragma unroll
            for (int nt = 0; nt < 4; ++nt)
                mma16816(acc[mt][nt], afr[buf][mt], bfr[buf][nt]);
    };

    // prologue: stages 0,1 in flight; frag(0, ks0) in regs
    issue(0, 0); cp_commit();
    issue(1, 1); cp_commit();
    cp_wait<1>();
    __syncthreads();
    ldfrags(0, 0, 0);

    int cur = 0;
    for (int t = 0; t < nch; ++t) {
        const int st  = t % 3;
        const int stn = (t + 1) % 3;

        // phase ks=0: prefetch (t, ks=1) frags; issue stage t+2; mma current
        ldfrags(cur ^ 1, st, 16);
        if (t + 2 < nch) issue(t + 2, (t + 2) % 3);
        cp_commit();
        domma(cur);
        cur ^= 1;

        // phase ks=1: advance stage under MMA shadow; prefetch (t+1, ks=0)
        if (t + 1 < nch) {
            cp_wait<1>();
            __syncthreads();
            ldfrags(cur ^ 1, stn, 0);
        }
        domma(cur);
        cur ^= 1;
    }

    // ---- epilogue ----
#pragma unroll
    for (int mt = 0; mt < 4; ++mt) {
        int r0 = m0 + warpm * 64 + mt * 16 + (lane >> 2);
        int r1 = r0 + 8;
#pragma unroll
        for (int nt = 0; nt < 4; ++nt) {
            int cl = warpn * 32 + nt * 8 + (lane & 3) * 2;
            int cg = n0 + cl;
            float b0 = sbias[cl], b1 = sbias[cl + 1];
            if (HALF_OUT) {
                __half* C = (__half*)Cv;
                if (r0 < M)
                    *(__half2*)(C + (size_t)r0 * Ntot + cg) =
                        __floats2half2_rn(acc[mt][nt][0] + b0, acc[mt][nt][1] + b1);
                if (r1 < M)
                    *(__half2*)(C + (size_t)r1 * Ntot + cg) =
                        __floats2half2_rn(acc[mt][nt][2] + b0, acc[mt][nt][3] + b1);
            } else {
                float* C = (float*)Cv;
                if (r0 < M)
                    *(float2*)(C + (size_t)r0 * Ntot + cg) =
                        make_float2(acc[mt][nt][0] + b0, acc[mt][nt][1] + b1);
                if (r1 < M)
                    *(float2*)(C + (size_t)r1 * Ntot + cg) =
                        make_float2(acc[mt][nt][2] + b0, acc[mt][nt][3] + b1);
            }
        }
    }
}

// ---------------------------------------------------------------------------
__global__ void prep_a16(const float* __restrict__ x, const float* __restrict__ h)
{
    int u = blockIdx.x * blockDim.x + threadIdx.x;
    if (u >= NNODES * 64) return;
    int n = u >> 6;
    int kq = (u & 63) << 3;
    const float* src = (kq < 256) ? (x + (size_t)n * 256 + kq)
                                  : (h + (size_t)n * 256 + kq - 256);
    float4 f0 = *(const float4*)(src);
    float4 f1 = *(const float4*)(src + 4);
    __half2 h0 = __floats2half2_rn(f0.x, f0.y);
    __half2 h1 = __floats2half2_rn(f0.z, f0.w);
    __half2 h2 = __floats2half2_rn(f1.x, f1.y);
    __half2 h3 = __floats2half2_rn(f1.z, f1.w);
    uint4 v;
    v.x = *(uint32_t*)&h0; v.y = *(uint32_t*)&h1;
    v.z = *(uint32_t*)&h2; v.w = *(uint32_t*)&h3;
    *(uint4*)(g_A16 + (size_t)n * 512 + kq) = v;
}

// ---------------------------------------------------------------------------
__global__ void pack_kernel(
    const float* __restrict__ Wi, const float* __restrict__ Wf,
    const float* __restrict__ Wc, const float* __restrict__ Wo,
    const float* __restrict__ Ti, const float* __restrict__ Tf,
    const float* __restrict__ Tc, const float* __restrict__ To,
    const float* __restrict__ bthi, const float* __restrict__ bthf,
    const float* __restrict__ bthc, const float* __restrict__ btho,
    const float* __restrict__ bi, const float* __restrict__ bf,
    const float* __restrict__ bc, const float* __restrict__ bo,
    const float* __restrict__ Wlin)
{
    int idx = blockIdx.x * blockDim.x + threadIdx.x;
    if (idx < 524288) {                       // g_Wt[n][k] = Wall[k][n]
        int n = idx >> 9, k = idx & 511;
        int g = n >> 8, jj = n & 255;
        float v;
        if (k < 256) {
            const float* W = (g == 0) ? Wi : (g == 1) ? Wf : (g == 2) ? Wc : Wo;
            v = W[k * 256 + jj];
        } else {
            const float* T = (g == 0) ? Ti : (g == 1) ? Tf : (g == 2) ? Tc : To;
            v = T[(k - 256) * 256 + jj];
        }
        g_Wt[idx] = __float2half_rn(v);
    } else if (idx < 524288 + 65536) {        // g_WlT[n][k] = Wlin[k][n]
        int i2 = idx - 524288;
        int n = i2 >> 8, k = i2 & 255;
        g_WlT[i2] = __float2half_rn(Wlin[k * 256 + n]);
    } else if (idx < 524288 + 65536 + 1024) { // g_bias
        int j = idx - 524288 - 65536;
        int g = j >> 8, jj = j & 255;
        const float* bth = (g == 0) ? bthi : (g == 1) ? bthf : (g == 2) ? bthc : btho;
        const float* bb  = (g == 0) ? bi   : (g == 1) ? bf   : (g == 2) ? bc   : bo;
        g_bias[j] = bth[jj] + bb[jj];
    }
}

// ---------------------------------------------------------------------------
__global__ void gates_kernel(const float* __restrict__ c_in,
                             const float* __restrict__ wci,
                             const float* __restrict__ wcf,
                             const float* __restrict__ wco,
                             float* __restrict__ h_out,
                             float* __restrict__ c_out)
{
    int u = blockIdx.x * blockDim.x + threadIdx.x;   // NNODES*32
    if (u >= NNODES * 32) return;
    int n = u >> 5;
    int j = (u & 31) << 3;
    const __half* P = g_P + (size_t)n * 1024;

    uint4 vi = *(const uint4*)(P + j);
    uint4 vf = *(const uint4*)(P + 256 + j);
    uint4 vc = *(const uint4*)(P + 512 + j);
    uint4 vo = *(const uint4*)(P + 768 + j);
    float4 c0 = *(const float4*)(c_in + (size_t)n * 256 + j);
    float4 c1 = *(const float4*)(c_in + (size_t)n * 256 + j + 4);
    float4 wi0 = *(const float4*)(wci + j), wi1 = *(const float4*)(wci + j + 4);
    float4 wf0 = *(const float4*)(wcf + j), wf1 = *(const float4*)(wcf + j + 4);
    float4 wo0 = *(const float4*)(wco + j), wo1 = *(const float4*)(wco + j + 4);

    float pi[8], pf[8], pc[8], po[8];
    {
        const uint32_t* a = &vi.x;
        const uint32_t* b = &vf.x;
        const uint32_t* cc = &vc.x;
        const uint32_t* d = &vo.x;
#pragma unroll
        for (int q = 0; q < 4; ++q) {
            float2 t;
            t = __half22float2(*(const __half2*)&a[q]);  pi[2*q] = t.x; pi[2*q+1] = t.y;
            t = __half22float2(*(const __half2*)&b[q]);  pf[2*q] = t.x; pf[2*q+1] = t.y;
            t = __half22float2(*(const __half2*)&cc[q]); pc[2*q] = t.x; pc[2*q+1] = t.y;
            t = __half22float2(*(const __half2*)&d[q]);  po[2*q] = t.x; po[2*q+1] = t.y;
        }
    }
    float cv[8]  = {c0.x, c0.y, c0.z, c0.w, c1.x, c1.y, c1.z, c1.w};
    float wia[8] = {wi0.x, wi0.y, wi0.z, wi0.w, wi1.x, wi1.y, wi1.z, wi1.w};
    float wfa[8] = {wf0.x, wf0.y, wf0.z, wf0.w, wf1.x, wf1.y, wf1.z, wf1.w};
    float woa[8] = {wo0.x, wo0.y, wo0.z, wo0.w, wo1.x, wo1.y, wo1.z, wo1.w};

    float H[8], Cn[8];
#pragma unroll
    for (int e = 0; e < 8; ++e) {
        float I = sigf(pi[e] + wia[e] * cv[e]);
        float F = sigf(pf[e] + wfa[e] * cv[e]);
        float T = tanf_(pc[e]);
        Cn[e] = F * cv[e] + I * T;
        float O = sigf(po[e] + woa[e] * Cn[e]);
        H[e] = O * tanf_(Cn[e]);
    }

    size_t off = (size_t)n * 256 + j;
    *(float4*)(h_out + off)     = make_float4(H[0], H[1], H[2], H[3]);
    *(float4*)(h_out + off + 4) = make_float4(H[4], H[5], H[6], H[7]);
    *(float4*)(c_out + off)     = make_float4(Cn[0], Cn[1], Cn[2], Cn[3]);
    *(float4*)(c_out + off + 4) = make_float4(Cn[4], Cn[5], Cn[6], Cn[7]);

    uint4 rv;
    __half2 r01 = __floats2half2_rn(fmaxf(H[0], 0.f), fmaxf(H[1], 0.f));
    __half2 r23 = __floats2half2_rn(fmaxf(H[2], 0.f), fmaxf(H[3], 0.f));
    __half2 r45 = __floats2half2_rn(fmaxf(H[4], 0.f), fmaxf(H[5], 0.f));
    __half2 r67 = __floats2half2_rn(fmaxf(H[6], 0.f), fmaxf(H[7], 0.f));
    rv.x = *(uint32_t*)&r01; rv.y = *(uint32_t*)&r23;
    rv.z = *(uint32_t*)&r45; rv.w = *(uint32_t*)&r67;
    *(uint4*)(g_R + off) = rv;
}

// ---------------------------------------------------------------------------
extern "C" void kernel_launch(void* const* d_in, const int* in_sizes, int n_in,
                              void* d_out, int out_size)
{
    const float* x    = (const float*)d_in[0];
    // d_in[1] edge_index, d_in[2] edge_weight -> unused (K=1 ChebConv)
    const float* h    = (const float*)d_in[3];
    const float* c    = (const float*)d_in[4];
    const float* Wi   = (const float*)d_in[5];
    const float* Wf   = (const float*)d_in[6];
    const float* Wc   = (const float*)d_in[7];
    const float* Wo   = (const float*)d_in[8];
    const float* Ti   = (const float*)d_in[9];
    const float* Tf   = (const float*)d_in[10];
    const float* Tc   = (const float*)d_in[11];
    const float* To   = (const float*)d_in[12];
    const float* bthi = (const float*)d_in[13];
    const float* bthf = (const float*)d_in[14];
    const float* bthc = (const float*)d_in[15];
    const float* btho = (const float*)d_in[16];
    const float* wci  = (const float*)d_in[17];
    const float* wcf  = (const float*)d_in[18];
    const float* wco  = (const float*)d_in[19];
    const float* bi   = (const float*)d_in[20];
    const float* bf   = (const float*)d_in[21];
    const float* bc   = (const float*)d_in[22];
    const float* bo   = (const float*)d_in[23];
    const float* Wlin = (const float*)d_in[24];
    const float* blin = (const float*)d_in[25];
    float* out = (float*)d_out;

    float *pBias;
    __half *pA16, *pP, *pWt, *pWlT, *pR;
    cudaGetSymbolAddress((void**)&pBias, g_bias);
    cudaGetSymbolAddress((void**)&pA16, g_A16);
    cudaGetSymbolAddress((void**)&pP, g_P);
    cudaGetSymbolAddress((void**)&pWt, g_Wt);
    cudaGetSymbolAddress((void**)&pWlT, g_WlT);
    cudaGetSymbolAddress((void**)&pR, g_R);

    cudaFuncSetAttribute(hmma_gemm<true>,
                         cudaFuncAttributeMaxDynamicSharedMemorySize, SMEMG);
    cudaFuncSetAttribute(hmma_gemm<false>,
                         cudaFuncAttributeMaxDynamicSharedMemorySize, SMEMG);

    // one-time host-side stream/event setup (no device memory)
    static cudaStream_t s2 = nullptr;
    static cudaEvent_t evFork, evPack;
    if (!s2) {
        cudaStreamCreateWithFlags(&s2, cudaStreamNonBlocking);
        cudaEventCreateWithFlags(&evFork, cudaEventDisableTiming);
        cudaEventCreateWithFlags(&evPack, cudaEventDisableTiming);
    }

    // pack (s2) overlapped with prep (default)
    cudaEventRecord(evFork, 0);
    cudaStreamWaitEvent(s2, evFork, 0);
    pack_kernel<<<(524288 + 65536 + 1024 + 255) / 256, 256, 0, s2>>>(
        Wi, Wf, Wc, Wo, Ti, Tf, Tc, To,
        bthi, bthf, bthc, btho, bi, bf, bc, bo, Wlin);
    cudaEventRecord(evPack, s2);

    prep_a16<<<(NNODES * 64 + 255) / 256, 256>>>(x, h);
    cudaStreamWaitEvent(0, evPack, 0);

    const size_t elems = (size_t)NNODES * 256;

    // GEMM1: P = A16 @ Wt^T + bias
    hmma_gemm<true><<<dim3(8, (NNODES + 127) / 128), 256, SMEMG>>>(
        pA16, pWt, pP, pBias, NNODES, 1024, 512);

    // gates -> h0, c0, R
    gates_kernel<<<(NNODES * 32 + 255) / 256, 256>>>(
        c, wci, wcf, wco, out + elems, out + 2 * elems);

    // GEMM2: out = R @ WlinT^T + b_lin
    hmma_gemm<false><<<dim3(2, (NNODES + 127) / 128), 256, SMEMG>>>(
        pR, pWlT, out, blin, NNODES, 256, 256);
}

// round 10
// speedup vs baseline: 1.7159x; 1.0322x over previous
#include <cuda_runtime.h>
#include <cuda_fp16.h>
#include <stdint.h>
#include <math.h>

// ---------------------------------------------------------------------------
// GCLSTM (K=1 ChebConv -> edge data unused). fp16 HMMA path.
//   pack (stream2) || prep A16 = fp16([x|h]) (default)
//   GEMM1: P(fp16) = A16 @ Wt^T + bias   (M=50000, N=1024, K=512) BN=256
//   gates: h0, c0 (fp32), R (fp16)
//   GEMM2: out = R @ WlinT^T + b_lin     (M=50000, N=256, K=256)  BN=256
// GEMM: BM=128, BN=256, BK=32, 8 warps (2m x 4n), warp 64x64, 4-stage cp.async.
// Output tuple: [out | h0 | c0], each 50000*256 fp32.
// ---------------------------------------------------------------------------

#define NNODES 50000

__device__ __half g_A16[(size_t)NNODES * 512];
__device__ __half g_P[(size_t)NNODES * 1024];
__device__ __half g_R[(size_t)NNODES * 256];
__device__ __half g_Wt[1024 * 512];
__device__ __half g_WlT[256 * 256];
__device__ float  g_bias[1024];

// ---------------------------------------------------------------------------
__device__ __forceinline__ uint32_t smem_u32(const void* p) {
    uint32_t a;
    asm("{ .reg .u64 t; cvta.to.shared.u64 t, %1; cvt.u32.u64 %0, t; }"
        : "=r"(a) : "l"(p));
    return a;
}
__device__ __forceinline__ void ldm4(uint32_t* a, uint32_t addr) {
    asm volatile("ldmatrix.sync.aligned.m8n8.x4.shared.b16 {%0,%1,%2,%3}, [%4];"
        : "=r"(a[0]), "=r"(a[1]), "=r"(a[2]), "=r"(a[3]) : "r"(addr));
}
__device__ __forceinline__ void mma16816(float* d, const uint32_t* a, const uint32_t* b) {
    asm volatile(
        "mma.sync.aligned.m16n8k16.row.col.f32.f16.f16.f32 "
        "{%0,%1,%2,%3},{%4,%5,%6,%7},{%8,%9},{%0,%1,%2,%3};"
        : "+f"(d[0]), "+f"(d[1]), "+f"(d[2]), "+f"(d[3])
        : "r"(a[0]), "r"(a[1]), "r"(a[2]), "r"(a[3]), "r"(b[0]), "r"(b[1]));
}
__device__ __forceinline__ void cp16(uint32_t dst, const void* src) {
    asm volatile("cp.async.cg.shared.global [%0], [%1], 16;" :: "r"(dst), "l"(src));
}
__device__ __forceinline__ void cp_commit() { asm volatile("cp.async.commit_group;"); }
template <int N>
__device__ __forceinline__ void cp_wait() {
    asm volatile("cp.async.wait_group %0;" :: "n"(N));
}

__device__ __forceinline__ float sigf(float x)  { return 1.f / (1.f + __expf(-x)); }
__device__ __forceinline__ float tanf_(float x) { return 2.f / (1.f + __expf(-2.f * x)) - 1.f; }

// ---------------------------------------------------------------------------
// HMMA GEMM: BM=128, BN=256, BK=32, 8 warps (2m x 4n), warp tile 64x64,
// 4-stage cp.async. A fp16 [M,K], B fp16 [Ntot,K], C = A @ B^T + bias.
// ---------------------------------------------------------------------------
#define ABUF (128 * 80)
#define BBUF (256 * 80)
#define STG  (ABUF + BBUF)
#define SMEM_DYN (4 * STG)           // 122880 B

template <bool HALF_OUT>
__global__ void __launch_bounds__(256, 1)
hmma_gemm(const __half* __restrict__ A16, const __half* __restrict__ B,
          void* __restrict__ Cv, const float* __restrict__ bias,
          int M, int Ntot, int K)
{
    extern __shared__ __align__(16) char usm[];
    __shared__ float sbias[256];

    const int tid  = threadIdx.x;
    const int lane = tid & 31;
    const int wid  = tid >> 5;
    const int warpm = wid >> 2;
    const int warpn = wid & 3;
    const int m0 = blockIdx.y * 128;
    const int n0 = blockIdx.x * 256;

    const uint32_t smb = smem_u32(usm);
    sbias[tid] = bias[n0 + tid];

    float acc[4][8][4];
#pragma unroll
    for (int mt = 0; mt < 4; ++mt)
#pragma unroll
        for (int nt = 0; nt < 8; ++nt)
#pragma unroll
            for (int e = 0; e < 4; ++e) acc[mt][nt][e] = 0.f;

    const int nch = K >> 5;

    auto issue = [&](int kc, int st) {
        const uint32_t ab = smb + st * STG;
        const uint32_t bb = ab + ABUF;
#pragma unroll
        for (int q = 0; q < 2; ++q) {
            int u = tid + q * 256;
            int r = u >> 2, kq = u & 3;
            int gr = m0 + r;
            if (gr < M)
                cp16(ab + r * 80 + kq * 16,
                     A16 + (size_t)gr * K + kc * 32 + kq * 8);
        }
#pragma unroll
        for (int q = 0; q < 4; ++q) {
            int u = tid + q * 256;
            int r = u >> 2, kq = u & 3;
            cp16(bb + r * 80 + kq * 16,
                 B + (size_t)(n0 + r) * K + kc * 32 + kq * 8);
        }
    };

    issue(0, 0); cp_commit();
    issue(1, 1); cp_commit();
    issue(2, 2); cp_commit();
    cp_wait<2>();
    __syncthreads();

    const int arow = warpm * 64 + (lane & 15);
    const int aoff = (lane >> 4) * 8;
    const int brow = warpn * 64 + ((lane >> 4) << 3) + (lane & 7);
    const int boff = ((lane >> 3) & 1) * 8;

    for (int t = 0; t < nch; ++t) {
        if (t + 3 < nch) issue(t + 3, (t + 3) & 3);
        cp_commit();

        const int st = t & 3;
        const uint32_t ab = smb + st * STG + arow * 80;
        const uint32_t bb = smb + st * STG + ABUF + brow * 80;
#pragma unroll
        for (int ks = 0; ks < 2; ++ks) {
            const int k0 = ks * 16;
            uint32_t afr[4][4], bfr[8][2];
#pragma unroll
            for (int mt = 0; mt < 4; ++mt)
                ldm4(afr[mt], ab + mt * 16 * 80 + (k0 + aoff) * 2);
#pragma unroll
            for (int np = 0; np < 4; ++np) {
                uint32_t f[4];
                ldm4(f, bb + np * 16 * 80 + (k0 + boff) * 2);
                bfr[np * 2][0] = f[0]; bfr[np * 2][1] = f[1];
                bfr[np * 2 + 1][0] = f[2]; bfr[np * 2 + 1][1] = f[3];
            }
#pragma unroll
            for (int mt = 0; mt < 4; ++mt)
#pragma unroll
                for (int nt = 0; nt < 8; ++nt)
                    mma16816(acc[mt][nt], afr[mt], bfr[nt]);
        }

        cp_wait<2>();
        __syncthreads();
    }

#pragma unroll
    for (int mt = 0; mt < 4; ++mt) {
        int r0 = m0 + warpm * 64 + mt * 16 + (lane >> 2);
        int r1 = r0 + 8;
#pragma unroll
        for (int nt = 0; nt < 8; ++nt) {
            int cl = warpn * 64 + nt * 8 + (lane & 3) * 2;
            int cg = n0 + cl;
            float b0 = sbias[cl], b1 = sbias[cl + 1];
            if (HALF_OUT) {
                __half* C = (__half*)Cv;
                if (r0 < M)
                    *(__half2*)(C + (size_t)r0 * Ntot + cg) =
                        __floats2half2_rn(acc[mt][nt][0] + b0, acc[mt][nt][1] + b1);
                if (r1 < M)
                    *(__half2*)(C + (size_t)r1 * Ntot + cg) =
                        __floats2half2_rn(acc[mt][nt][2] + b0, acc[mt][nt][3] + b1);
            } else {
                float* C = (float*)Cv;
                if (r0 < M)
                    *(float2*)(C + (size_t)r0 * Ntot + cg) =
                        make_float2(acc[mt][nt][0] + b0, acc[mt][nt][1] + b1);
                if (r1 < M)
                    *(float2*)(C + (size_t)r1 * Ntot + cg) =
                        make_float2(acc[mt][nt][2] + b0, acc[mt][nt][3] + b1);
            }
        }
    }
}

// ---------------------------------------------------------------------------
__global__ void prep_a16(const float* __restrict__ x, const float* __restrict__ h)
{
    int u = blockIdx.x * blockDim.x + threadIdx.x;
    if (u >= NNODES * 64) return;
    int n = u >> 6;
    int kq = (u & 63) << 3;
    const float* src = (kq < 256) ? (x + (size_t)n * 256 + kq)
                                  : (h + (size_t)n * 256 + kq - 256);
    float4 f0 = *(const float4*)(src);
    float4 f1 = *(const float4*)(src + 4);
    __half2 h0 = __floats2half2_rn(f0.x, f0.y);
    __half2 h1 = __floats2half2_rn(f0.z, f0.w);
    __half2 h2 = __floats2half2_rn(f1.x, f1.y);
    __half2 h3 = __floats2half2_rn(f1.z, f1.w);
    uint4 v;
    v.x = *(uint32_t*)&h0; v.y = *(uint32_t*)&h1;
    v.z = *(uint32_t*)&h2; v.w = *(uint32_t*)&h3;
    *(uint4*)(g_A16 + (size_t)n * 512 + kq) = v;
}

// ---------------------------------------------------------------------------
__global__ void pack_kernel(
    const float* __restrict__ Wi, const float* __restrict__ Wf,
    const float* __restrict__ Wc, const float* __restrict__ Wo,
    const float* __restrict__ Ti, const float* __restrict__ Tf,
    const float* __restrict__ Tc, const float* __restrict__ To,
    const float* __restrict__ bthi, const float* __restrict__ bthf,
    const float* __restrict__ bthc, const float* __restrict__ btho,
    const float* __restrict__ bi, const float* __restrict__ bf,
    const float* __restrict__ bc, const float* __restrict__ bo,
    const float* __restrict__ Wlin)
{
    int idx = blockIdx.x * blockDim.x + threadIdx.x;
    if (idx < 524288) {                       // g_Wt[n][k] = Wall[k][n]
        int n = idx >> 9, k = idx & 511;
        int g = n >> 8, jj = n & 255;
        float v;
        if (k < 256) {
            const float* W = (g == 0) ? Wi : (g == 1) ? Wf : (g == 2) ? Wc : Wo;
            v = W[k * 256 + jj];
        } else {
            const float* T = (g == 0) ? Ti : (g == 1) ? Tf : (g == 2) ? Tc : To;
            v = T[(k - 256) * 256 + jj];
        }
        g_Wt[idx] = __float2half_rn(v);
    } else if (idx < 524288 + 65536) {        // g_WlT[n][k] = Wlin[k][n]
        int i2 = idx - 524288;
        int n = i2 >> 8, k = i2 & 255;
        g_WlT[i2] = __float2half_rn(Wlin[k * 256 + n]);
    } else if (idx < 524288 + 65536 + 1024) { // g_bias
        int j = idx - 524288 - 65536;
        int g = j >> 8, jj = j & 255;
        const float* bth = (g == 0) ? bthi : (g == 1) ? bthf : (g == 2) ? bthc : btho;
        const float* bb  = (g == 0) ? bi   : (g == 1) ? bf   : (g == 2) ? bc   : bo;
        g_bias[j] = bth[jj] + bb[jj];
    }
}

// ---------------------------------------------------------------------------
__global__ void gates_kernel(const float* __restrict__ c_in,
                             const float* __restrict__ wci,
                             const float* __restrict__ wcf,
                             const float* __restrict__ wco,
                             float* __restrict__ h_out,
                             float* __restrict__ c_out)
{
    int u = blockIdx.x * blockDim.x + threadIdx.x;   // NNODES*32
    if (u >= NNODES * 32) return;
    int n = u >> 5;
    int j = (u & 31) << 3;
    const __half* P = g_P + (size_t)n * 1024;

    uint4 vi = *(const uint4*)(P + j);
    uint4 vf = *(const uint4*)(P + 256 + j);
    uint4 vc = *(const uint4*)(P + 512 + j);
    uint4 vo = *(const uint4*)(P + 768 + j);
    float4 c0 = *(const float4*)(c_in + (size_t)n * 256 + j);
    float4 c1 = *(const float4*)(c_in + (size_t)n * 256 + j + 4);
    float4 wi0 = *(const float4*)(wci + j), wi1 = *(const float4*)(wci + j + 4);
    float4 wf0 = *(const float4*)(wcf + j), wf1 = *(const float4*)(wcf + j + 4);
    float4 wo0 = *(const float4*)(wco + j), wo1 = *(const float4*)(wco + j + 4);

    float pi[8], pf[8], pc[8], po[8];
    {
        const uint32_t* a = &vi.x;
        const uint32_t* b = &vf.x;
        const uint32_t* cc = &vc.x;
        const uint32_t* d = &vo.x;
#pragma unroll
        for (int q = 0; q < 4; ++q) {
            float2 t;
            t = __half22float2(*(const __half2*)&a[q]);  pi[2*q] = t.x; pi[2*q+1] = t.y;
            t = __half22float2(*(const __half2*)&b[q]);  pf[2*q] = t.x; pf[2*q+1] = t.y;
            t = __half22float2(*(const __half2*)&cc[q]); pc[2*q] = t.x; pc[2*q+1] = t.y;
            t = __half22float2(*(const __half2*)&d[q]);  po[2*q] = t.x; po[2*q+1] = t.y;
        }
    }
    float cv[8]  = {c0.x, c0.y, c0.z, c0.w, c1.x, c1.y, c1.z, c1.w};
    float wia[8] = {wi0.x, wi0.y, wi0.z, wi0.w, wi1.x, wi1.y, wi1.z, wi1.w};
    float wfa[8] = {wf0.x, wf0.y, wf0.z, wf0.w, wf1.x, wf1.y, wf1.z, wf1.w};
    float woa[8] = {wo0.x, wo0.y, wo0.z, wo0.w, wo1.x, wo1.y, wo1.z, wo1.w};

    float H[8], Cn[8];
#pragma unroll
    for (int e = 0; e < 8; ++e) {
        float I = sigf(pi[e] + wia[e] * cv[e]);
        float F = sigf(pf[e] + wfa[e] * cv[e]);
        float T = tanf_(pc[e]);
        Cn[e] = F * cv[e] + I * T;
        float O = sigf(po[e] + woa[e] * Cn[e]);
        H[e] = O * tanf_(Cn[e]);
    }

    size_t off = (size_t)n * 256 + j;
    *(float4*)(h_out + off)     = make_float4(H[0], H[1], H[2], H[3]);
    *(float4*)(h_out + off + 4) = make_float4(H[4], H[5], H[6], H[7]);
    *(float4*)(c_out + off)     = make_float4(Cn[0], Cn[1], Cn[2], Cn[3]);
    *(float4*)(c_out + off + 4) = make_float4(Cn[4], Cn[5], Cn[6], Cn[7]);

    uint4 rv;
    __half2 r01 = __floats2half2_rn(fmaxf(H[0], 0.f), fmaxf(H[1], 0.f));
    __half2 r23 = __floats2half2_rn(fmaxf(H[2], 0.f), fmaxf(H[3], 0.f));
    __half2 r45 = __floats2half2_rn(fmaxf(H[4], 0.f), fmaxf(H[5], 0.f));
    __half2 r67 = __floats2half2_rn(fmaxf(H[6], 0.f), fmaxf(H[7], 0.f));
    rv.x = *(uint32_t*)&r01; rv.y = *(uint32_t*)&r23;
    rv.z = *(uint32_t*)&r45; rv.w = *(uint32_t*)&r67;
    *(uint4*)(g_R + off) = rv;
}

// ---------------------------------------------------------------------------
extern "C" void kernel_launch(void* const* d_in, const int* in_sizes, int n_in,
                              void* d_out, int out_size)
{
    const float* x    = (const float*)d_in[0];
    // d_in[1] edge_index, d_in[2] edge_weight -> unused (K=1 ChebConv)
    const float* h    = (const float*)d_in[3];
    const float* c    = (const float*)d_in[4];
    const float* Wi   = (const float*)d_in[5];
    const float* Wf   = (const float*)d_in[6];
    const float* Wc   = (const float*)d_in[7];
    const float* Wo   = (const float*)d_in[8];
    const float* Ti   = (const float*)d_in[9];
    const float* Tf   = (const float*)d_in[10];
    const float* Tc   = (const float*)d_in[11];
    const float* To   = (const float*)d_in[12];
    const float* bthi = (const float*)d_in[13];
    const float* bthf = (const float*)d_in[14];
    const float* bthc = (const float*)d_in[15];
    const float* btho = (const float*)d_in[16];
    const float* wci  = (const float*)d_in[17];
    const float* wcf  = (const float*)d_in[18];
    const float* wco  = (const float*)d_in[19];
    const float* bi   = (const float*)d_in[20];
    const float* bf   = (const float*)d_in[21];
    const float* bc   = (const float*)d_in[22];
    const float* bo   = (const float*)d_in[23];
    const float* Wlin = (const float*)d_in[24];
    const float* blin = (const float*)d_in[25];
    float* out = (float*)d_out;

    float *pBias;
    __half *pA16, *pP, *pWt, *pWlT, *pR;
    cudaGetSymbolAddress((void**)&pBias, g_bias);
    cudaGetSymbolAddress((void**)&pA16, g_A16);
    cudaGetSymbolAddress((void**)&pP, g_P);
    cudaGetSymbolAddress((void**)&pWt, g_Wt);
    cudaGetSymbolAddress((void**)&pWlT, g_WlT);
    cudaGetSymbolAddress((void**)&pR, g_R);

    cudaFuncSetAttribute(hmma_gemm<true>,
                         cudaFuncAttributeMaxDynamicSharedMemorySize, SMEM_DYN);
    cudaFuncSetAttribute(hmma_gemm<false>,
                         cudaFuncAttributeMaxDynamicSharedMemorySize, SMEM_DYN);

    // one-time host-side stream/event setup (no device memory)
    static cudaStream_t s2 = nullptr;
    static cudaEvent_t evFork, evPack;
    if (!s2) {
        cudaStreamCreateWithFlags(&s2, cudaStreamNonBlocking);
        cudaEventCreateWithFlags(&evFork, cudaEventDisableTiming);
        cudaEventCreateWithFlags(&evPack, cudaEventDisableTiming);
    }

    // pack (s2) overlapped with prep (default)
    cudaEventRecord(evFork, 0);
    cudaStreamWaitEvent(s2, evFork, 0);
    pack_kernel<<<(524288 + 65536 + 1024 + 255) / 256, 256, 0, s2>>>(
        Wi, Wf, Wc, Wo, Ti, Tf, Tc, To,
        bthi, bthf, bthc, btho, bi, bf, bc, bo, Wlin);
    cudaEventRecord(evPack, s2);

    prep_a16<<<(NNODES * 64 + 255) / 256, 256>>>(x, h);
    cudaStreamWaitEvent(0, evPack, 0);

    const size_t elems = (size_t)NNODES * 256;

    // GEMM1: P = A16 @ Wt^T + bias   grid (1024/256, ceil(M/128))
    hmma_gemm<true><<<dim3(4, (NNODES + 127) / 128), 256, SMEM_DYN>>>(
        pA16, pWt, pP, pBias, NNODES, 1024, 512);

    // gates -> h0, c0, R
    gates_kernel<<<(NNODES * 32 + 255) / 256, 256>>>(
        c, wci, wcf, wco, out + elems, out + 2 * elems);

    // GEMM2: out = R @ WlinT^T + b_lin   grid (256/256, ceil(M/128))
    hmma_gemm<false><<<dim3(1, (NNODES + 127) / 128), 256, SMEM_DYN>>>(
        pR, pWlT, out, blin, NNODES, 256, 256);
}

// round 11
// speedup vs baseline: 1.8064x; 1.0527x over previous
#include <cuda_runtime.h>
#include <cuda_fp16.h>
#include <stdint.h>
#include <math.h>

// ---------------------------------------------------------------------------
// GCLSTM (K=1 ChebConv -> edge data unused). fp16 HMMA path.
//   pack (stream2) overlapped with GEMM1 head.
//   GEMM1: P(fp16) = [x|h](fp32, converted in-loader) @ Wt^T + bias
//          (M=50000, N=1024, K=512) BN=256; A fp32 stays L2-resident across
//          the 4 N-blocks (blockIdx.x fastest) -> read from DRAM once.
//   gates: h0, c0 (fp32), R (fp16)
//   GEMM2: out = R @ WlinT^T + b_lin  (M=50000, N=256, K=256) BN=256
// GEMM: BM=128, BN=256, BK=32, 8 warps (2m x 4n), warp 64x64, 4-stage.
// Output tuple: [out | h0 | c0], each 50000*256 fp32.
// ---------------------------------------------------------------------------

#define NNODES 50000

__device__ __half g_P[(size_t)NNODES * 1024];
__device__ __half g_R[(size_t)NNODES * 256];
__device__ __half g_Wt[1024 * 512];
__device__ __half g_WlT[256 * 256];
__device__ float  g_bias[1024];

// ---------------------------------------------------------------------------
__device__ __forceinline__ uint32_t smem_u32(const void* p) {
    uint32_t a;
    asm("{ .reg .u64 t; cvta.to.shared.u64 t, %1; cvt.u32.u64 %0, t; }"
        : "=r"(a) : "l"(p));
    return a;
}
__device__ __forceinline__ void ldm4(uint32_t* a, uint32_t addr) {
    asm volatile("ldmatrix.sync.aligned.m8n8.x4.shared.b16 {%0,%1,%2,%3}, [%4];"
        : "=r"(a[0]), "=r"(a[1]), "=r"(a[2]), "=r"(a[3]) : "r"(addr));
}
__device__ __forceinline__ void mma16816(float* d, const uint32_t* a, const uint32_t* b) {
    asm volatile(
        "mma.sync.aligned.m16n8k16.row.col.f32.f16.f16.f32 "
        "{%0,%1,%2,%3},{%4,%5,%6,%7},{%8,%9},{%0,%1,%2,%3};"
        : "+f"(d[0]), "+f"(d[1]), "+f"(d[2]), "+f"(d[3])
        : "r"(a[0]), "r"(a[1]), "r"(a[2]), "r"(a[3]), "r"(b[0]), "r"(b[1]));
}
__device__ __forceinline__ void cp16(uint32_t dst, const void* src) {
    asm volatile("cp.async.cg.shared.global [%0], [%1], 16;" :: "r"(dst), "l"(src));
}
__device__ __forceinline__ void cp_commit() { asm volatile("cp.async.commit_group;"); }
template <int N>
__device__ __forceinline__ void cp_wait() {
    asm volatile("cp.async.wait_group %0;" :: "n"(N));
}

__device__ __forceinline__ float sigf(float x)  { return 1.f / (1.f + __expf(-x)); }
__device__ __forceinline__ float tanf_(float x) { return 2.f / (1.f + __expf(-2.f * x)) - 1.f; }

// ---------------------------------------------------------------------------
// HMMA GEMM: BM=128, BN=256, BK=32, 8 warps (2m x 4n), warp tile 64x64,
// 4-stage. B via cp.async always.
// G1=true : A = [x|h] fp32, LDG->cvt->STS loader (fetch early / store late),
//           C fp16 (P).
// G1=false: A fp16 via cp.async, C fp32.
// ---------------------------------------------------------------------------
#define ABUF (128 * 80)
#define BBUF (256 * 80)
#define STG  (ABUF + BBUF)
#define SMEM_DYN (4 * STG)           // 122880 B

template <bool G1>
__global__ void __launch_bounds__(256, 1)
hmma_gemm(const float* __restrict__ Ax, const float* __restrict__ Ah,
          const __half* __restrict__ A16, const __half* __restrict__ B,
          void* __restrict__ Cv, const float* __restrict__ bias,
          int M, int Ntot, int K)
{
    extern __shared__ __align__(16) char usm[];
    __shared__ float sbias[256];

    const int tid  = threadIdx.x;
    const int lane = tid & 31;
    const int wid  = tid >> 5;
    const int warpm = wid >> 2;
    const int warpn = wid & 3;
    const int m0 = blockIdx.y * 128;
    const int n0 = blockIdx.x * 256;

    const uint32_t smb = smem_u32(usm);
    sbias[tid] = bias[n0 + tid];

    float acc[4][8][4];
#pragma unroll
    for (int mt = 0; mt < 4; ++mt)
#pragma unroll
        for (int nt = 0; nt < 8; ++nt)
#pragma unroll
            for (int e = 0; e < 4; ++e) acc[mt][nt][e] = 0.f;

    const int nch = K >> 5;

    // ---- A loaders ----
    float4 areg[4];                       // G1 staging (fp32)
    const int a_r  = tid >> 3;            // row 0..31 base (tid/8), rows via +32
    const int a_fq = tid & 7;             // float4 index 0..7 within 32 cols

    auto fetchA32 = [&](int kc) {         // G1: LDG fp32 into regs
        const float* src = (kc < 8) ? Ax : Ah;
        const int cb = (kc & 7) * 32;
#pragma unroll
        for (int q = 0; q < 4; ++q) {
            int r = a_r + q * 32;
            int gr = m0 + r;
            areg[q] = make_float4(0.f, 0.f, 0.f, 0.f);
            if (gr < M)
                areg[q] = *(const float4*)(src + (size_t)gr * 256 + cb + a_fq * 4);
        }
    };
    auto storeA32 = [&](int st) {         // G1: cvt + STS.64
        const uint32_t ab = smb + st * STG;
#pragma unroll
        for (int q = 0; q < 4; ++q) {
            int r = a_r + q * 32;
            __half2 h0 = __floats2half2_rn(areg[q].x, areg[q].y);
            __half2 h1 = __floats2half2_rn(areg[q].z, areg[q].w);
            uint2 v;
            v.x = *(uint32_t*)&h0;
            v.y = *(uint32_t*)&h1;
            *(uint2*)(usm + st * STG + r * 80 + a_fq * 8) = v;
        }
        (void)ab;
    };
    auto issueA16 = [&](int kc, int st) { // !G1: cp.async fp16
#pragma unroll
        for (int q = 0; q < 2; ++q) {
            int u = tid + q * 256;
            int r = u >> 2, kq = u & 3;
            int gr = m0 + r;
            if (gr < M)
                cp16(smb + st * STG + r * 80 + kq * 16,
                     A16 + (size_t)gr * K + kc * 32 + kq * 8);
        }
    };
    auto issueB = [&](int kc, int st) {
        const uint32_t bb = smb + st * STG + ABUF;
#pragma unroll
        for (int q = 0; q < 4; ++q) {
            int u = tid + q * 256;
            int r = u >> 2, kq = u & 3;
            cp16(bb + r * 80 + kq * 16,
                 B + (size_t)(n0 + r) * K + kc * 32 + kq * 8);
        }
    };

    // ---- prologue: stages 0..2 ----
    if (G1) {
        fetchA32(0); storeA32(0);
        fetchA32(1); storeA32(1);
        fetchA32(2); storeA32(2);
        issueB(0, 0); cp_commit();
        issueB(1, 1); cp_commit();
        issueB(2, 2); cp_commit();
    } else {
        issueA16(0, 0); issueB(0, 0); cp_commit();
        issueA16(1, 1); issueB(1, 1); cp_commit();
        issueA16(2, 2); issueB(2, 2); cp_commit();
    }
    cp_wait<2>();
    __syncthreads();

    const int arow = warpm * 64 + (lane & 15);
    const int aoff = (lane >> 4) * 8;
    const int brow = warpn * 64 + ((lane >> 4) << 3) + (lane & 7);
    const int boff = ((lane >> 3) & 1) * 8;

    for (int t = 0; t < nch; ++t) {
        const bool pf = (t + 3 < nch);
        if (pf) {
            if (G1) fetchA32(t + 3);
            else    issueA16(t + 3, (t + 3) & 3);
            issueB(t + 3, (t + 3) & 3);
        }
        cp_commit();

        const int st = t & 3;
        const uint32_t ab = smb + st * STG + arow * 80;
        const uint32_t bb = smb + st * STG + ABUF + brow * 80;
#pragma unroll
        for (int ks = 0; ks < 2; ++ks) {
            const int k0 = ks * 16;
            uint32_t afr[4][4], bfr[8][2];
#pragma unroll
            for (int mt = 0; mt < 4; ++mt)
                ldm4(afr[mt], ab + mt * 16 * 80 + (k0 + aoff) * 2);
#pragma unroll
            for (int np = 0; np < 4; ++np) {
                uint32_t f[4];
                ldm4(f, bb + np * 16 * 80 + (k0 + boff) * 2);
                bfr[np * 2][0] = f[0]; bfr[np * 2][1] = f[1];
                bfr[np * 2 + 1][0] = f[2]; bfr[np * 2 + 1][1] = f[3];
            }
#pragma unroll
            for (int mt = 0; mt < 4; ++mt)
#pragma unroll
                for (int nt = 0; nt < 8; ++nt)
                    mma16816(acc[mt][nt], afr[mt], bfr[nt]);
        }

        if (G1 && pf) storeA32((t + 3) & 3);   // buffer (t-1)&3: readers done
        cp_wait<2>();
        __syncthreads();
    }

    // ---- epilogue ----
#pragma unroll
    for (int mt = 0; mt < 4; ++mt) {
        int r0 = m0 + warpm * 64 + mt * 16 + (lane >> 2);
        int r1 = r0 + 8;
#pragma unroll
        for (int nt = 0; nt < 8; ++nt) {
            int cl = warpn * 64 + nt * 8 + (lane & 3) * 2;
            int cg = n0 + cl;
            float b0 = sbias[cl], b1 = sbias[cl + 1];
            if (G1) {
                __half* C = (__half*)Cv;
                if (r0 < M)
                    *(__half2*)(C + (size_t)r0 * Ntot + cg) =
                        __floats2half2_rn(acc[mt][nt][0] + b0, acc[mt][nt][1] + b1);
                if (r1 < M)
                    *(__half2*)(C + (size_t)r1 * Ntot + cg) =
                        __floats2half2_rn(acc[mt][nt][2] + b0, acc[mt][nt][3] + b1);
            } else {
                float* C = (float*)Cv;
                if (r0 < M)
                    *(float2*)(C + (size_t)r0 * Ntot + cg) =
                        make_float2(acc[mt][nt][0] + b0, acc[mt][nt][1] + b1);
                if (r1 < M)
                    *(float2*)(C + (size_t)r1 * Ntot + cg) =
                        make_float2(acc[mt][nt][2] + b0, acc[mt][nt][3] + b1);
            }
        }
    }
}

// ---------------------------------------------------------------------------
__global__ void pack_kernel(
    const float* __restrict__ Wi, const float* __restrict__ Wf,
    const float* __restrict__ Wc, const float* __restrict__ Wo,
    const float* __restrict__ Ti, const float* __restrict__ Tf,
    const float* __restrict__ Tc, const float* __restrict__ To,
    const float* __restrict__ bthi, const float* __restrict__ bthf,
    const float* __restrict__ bthc, const float* __restrict__ btho,
    const float* __restrict__ bi, const float* __restrict__ bf,
    const float* __restrict__ bc, const float* __restrict__ bo,
    const float* __restrict__ Wlin)
{
    int idx = blockIdx.x * blockDim.x + threadIdx.x;
    if (idx < 524288) {                       // g_Wt[n][k] = Wall[k][n]
        int n = idx >> 9, k = idx & 511;
        int g = n >> 8, jj = n & 255;
        float v;
        if (k < 256) {
            const float* W = (g == 0) ? Wi : (g == 1) ? Wf : (g == 2) ? Wc : Wo;
            v = W[k * 256 + jj];
        } else {
            const float* T = (g == 0) ? Ti : (g == 1) ? Tf : (g == 2) ? Tc : To;
            v = T[(k - 256) * 256 + jj];
        }
        g_Wt[idx] = __float2half_rn(v);
    } else if (idx < 524288 + 65536) {        // g_WlT[n][k] = Wlin[k][n]
        int i2 = idx - 524288;
        int n = i2 >> 8, k = i2 & 255;
        g_WlT[i2] = __float2half_rn(Wlin[k * 256 + n]);
    } else if (idx < 524288 + 65536 + 1024) { // g_bias
        int j = idx - 524288 - 65536;
        int g = j >> 8, jj = j & 255;
        const float* bth = (g == 0) ? bthi : (g == 1) ? bthf : (g == 2) ? bthc : btho;
        const float* bb  = (g == 0) ? bi   : (g == 1) ? bf   : (g == 2) ? bc   : bo;
        g_bias[j] = bth[jj] + bb[jj];
    }
}

// ---------------------------------------------------------------------------
__global__ void gates_kernel(const float* __restrict__ c_in,
                             const float* __restrict__ wci,
                             const float* __restrict__ wcf,
                             const float* __restrict__ wco,
                             float* __restrict__ h_out,
                             float* __restrict__ c_out)
{
    int u = blockIdx.x * blockDim.x + threadIdx.x;   // NNODES*32
    if (u >= NNODES * 32) return;
    int n = u >> 5;
    int j = (u & 31) << 3;
    const __half* P = g_P + (size_t)n * 1024;

    uint4 vi = *(const uint4*)(P + j);
    uint4 vf = *(const uint4*)(P + 256 + j);
    uint4 vc = *(const uint4*)(P + 512 + j);
    uint4 vo = *(const uint4*)(P + 768 + j);
    float4 c0 = *(const float4*)(c_in + (size_t)n * 256 + j);
    float4 c1 = *(const float4*)(c_in + (size_t)n * 256 + j + 4);
    float4 wi0 = *(const float4*)(wci + j), wi1 = *(const float4*)(wci + j + 4);
    float4 wf0 = *(const float4*)(wcf + j), wf1 = *(const float4*)(wcf + j + 4);
    float4 wo0 = *(const float4*)(wco + j), wo1 = *(const float4*)(wco + j + 4);

    float pi[8], pf[8], pc[8], po[8];
    {
        const uint32_t* a = &vi.x;
        const uint32_t* b = &vf.x;
        const uint32_t* cc = &vc.x;
        const uint32_t* d = &vo.x;
#pragma unroll
        for (int q = 0; q < 4; ++q) {
            float2 t;
            t = __half22float2(*(const __half2*)&a[q]);  pi[2*q] = t.x; pi[2*q+1] = t.y;
            t = __half22float2(*(const __half2*)&b[q]);  pf[2*q] = t.x; pf[2*q+1] = t.y;
            t = __half22float2(*(const __half2*)&cc[q]); pc[2*q] = t.x; pc[2*q+1] = t.y;
            t = __half22float2(*(const __half2*)&d[q]);  po[2*q] = t.x; po[2*q+1] = t.y;
        }
    }
    float cv[8]  = {c0.x, c0.y, c0.z, c0.w, c1.x, c1.y, c1.z, c1.w};
    float wia[8] = {wi0.x, wi0.y, wi0.z, wi0.w, wi1.x, wi1.y, wi1.z, wi1.w};
    float wfa[8] = {wf0.x, wf0.y, wf0.z, wf0.w, wf1.x, wf1.y, wf1.z, wf1.w};
    float woa[8] = {wo0.x, wo0.y, wo0.z, wo0.w, wo1.x, wo1.y, wo1.z, wo1.w};

    float H[8], Cn[8];
#pragma unroll
    for (int e = 0; e < 8; ++e) {
        float I = sigf(pi[e] + wia[e] * cv[e]);
        float F = sigf(pf[e] + wfa[e] * cv[e]);
        float T = tanf_(pc[e]);
        Cn[e] = F * cv[e] + I * T;
        float O = sigf(po[e] + woa[e] * Cn[e]);
        H[e] = O * tanf_(Cn[e]);
    }

    size_t off = (size_t)n * 256 + j;
    *(float4*)(h_out + off)     = make_float4(H[0], H[1], H[2], H[3]);
    *(float4*)(h_out + off + 4) = make_float4(H[4], H[5], H[6], H[7]);
    *(float4*)(c_out + off)     = make_float4(Cn[0], Cn[1], Cn[2], Cn[3]);
    *(float4*)(c_out + off + 4) = make_float4(Cn[4], Cn[5], Cn[6], Cn[7]);

    uint4 rv;
    __half2 r01 = __floats2half2_rn(fmaxf(H[0], 0.f), fmaxf(H[1], 0.f));
    __half2 r23 = __floats2half2_rn(fmaxf(H[2], 0.f), fmaxf(H[3], 0.f));
    __half2 r45 = __floats2half2_rn(fmaxf(H[4], 0.f), fmaxf(H[5], 0.f));
    __half2 r67 = __floats2half2_rn(fmaxf(H[6], 0.f), fmaxf(H[7], 0.f));
    rv.x = *(uint32_t*)&r01; rv.y = *(uint32_t*)&r23;
    rv.z = *(uint32_t*)&r45; rv.w = *(uint32_t*)&r67;
    *(uint4*)(g_R + off) = rv;
}

// ---------------------------------------------------------------------------
extern "C" void kernel_launch(void* const* d_in, const int* in_sizes, int n_in,
                              void* d_out, int out_size)
{
    const float* x    = (const float*)d_in[0];
    // d_in[1] edge_index, d_in[2] edge_weight -> unused (K=1 ChebConv)
    const float* h    = (const float*)d_in[3];
    const float* c    = (const float*)d_in[4];
    const float* Wi   = (const float*)d_in[5];
    const float* Wf   = (const float*)d_in[6];
    const float* Wc   = (const float*)d_in[7];
    const float* Wo   = (const float*)d_in[8];
    const float* Ti   = (const float*)d_in[9];
    const float* Tf   = (const float*)d_in[10];
    const float* Tc   = (const float*)d_in[11];
    const float* To   = (const float*)d_in[12];
    const float* bthi = (const float*)d_in[13];
    const float* bthf = (const float*)d_in[14];
    const float* bthc = (const float*)d_in[15];
    const float* btho = (const float*)d_in[16];
    const float* wci  = (const float*)d_in[17];
    const float* wcf  = (const float*)d_in[18];
    const float* wco  = (const float*)d_in[19];
    const float* bi   = (const float*)d_in[20];
    const float* bf   = (const float*)d_in[21];
    const float* bc   = (const float*)d_in[22];
    const float* bo   = (const float*)d_in[23];
    const float* Wlin = (const float*)d_in[24];
    const float* blin = (const float*)d_in[25];
    float* out = (float*)d_out;

    float *pBias;
    __half *pP, *pWt, *pWlT, *pR;
    cudaGetSymbolAddress((void**)&pBias, g_bias);
    cudaGetSymbolAddress((void**)&pP, g_P);
    cudaGetSymbolAddress((void**)&pWt, g_Wt);
    cudaGetSymbolAddress((void**)&pWlT, g_WlT);
    cudaGetSymbolAddress((void**)&pR, g_R);

    cudaFuncSetAttribute(hmma_gemm<true>,
                         cudaFuncAttributeMaxDynamicSharedMemorySize, SMEM_DYN);
    cudaFuncSetAttribute(hmma_gemm<false>,
                         cudaFuncAttributeMaxDynamicSharedMemorySize, SMEM_DYN);

    // pack weights/bias (must precede GEMM1; small: ~590K elements)
    pack_kernel<<<(524288 + 65536 + 1024 + 255) / 256, 256>>>(
        Wi, Wf, Wc, Wo, Ti, Tf, Tc, To,
        bthi, bthf, bthc, btho, bi, bf, bc, bo, Wlin);

    const size_t elems = (size_t)NNODES * 256;

    // GEMM1: P = [x|h] @ Wt^T + bias (A converted in-loader, no prep pass)
    hmma_gemm<true><<<dim3(4, (NNODES + 127) / 128), 256, SMEM_DYN>>>(
        x, h, nullptr, pWt, pP, pBias, NNODES, 1024, 512);

    // gates -> h0, c0, R
    gates_kernel<<<(NNODES * 32 + 255) / 256, 256>>>(
        c, wci, wcf, wco, out + elems, out + 2 * elems);

    // GEMM2: out = R @ WlinT^T + b_lin
    hmma_gemm<false><<<dim3(1, (NNODES + 127) / 128), 256, SMEM_DYN>>>(
        nullptr, nullptr, pR, pWlT, out, blin, NNODES, 256, 256);
}